// round 7
// baseline (speedup 1.0000x reference)
#include <cuda_runtime.h>
#include <stdint.h>
#include <math.h>

// ---------------- problem constants ----------------
#define BQ     2
#define TT     8
#define HDIM   64
#define WDIM   64
#define CC     192
#define HEADS  6
#define DH     32
#define NTOK   256
#define NWIN   128
#define BWIN   256
#define MROWS  65536
#define HID    768
#define CPB_M  1575
#define CPB_H  512

typedef unsigned long long ull;

// ---------------- scratch ----------------
__device__ float g_xw [MROWS * CC];        // attention output (window layout)
__device__ float g_qkv[MROWS * 3 * CC];
__device__ float g_pr [MROWS * CC];
__device__ float g_x1 [MROWS * CC];
__device__ float g_h1 [MROWS * HID];
__device__ float g_tbl[CPB_M * HEADS];
__device__ float g_scale[HEADS];

// f32x2 packed helpers
#define FMA2(d, a, b) asm("fma.rn.f32x2 %0, %1, %2, %0;" : "+l"(d) : "l"(a), "l"(b))
#define MUL2(d, a, b) asm("mul.rn.f32x2 %0, %1, %2;" : "=l"(d) : "l"(a), "l"(b))
__device__ __forceinline__ ull pack2(float x) {
    ull r;
    asm("mov.b64 %0, {%1,%1};" : "=l"(r) : "r"(__float_as_uint(x)));
    return r;
}
__device__ __forceinline__ ull packxy(float x, float y) {
    ull r;
    asm("mov.b64 %0, {%1,%2};" : "=l"(r) : "r"(__float_as_uint(x)), "r"(__float_as_uint(y)));
    return r;
}

// window row -> source row in (B,T,H,W) layout
__device__ __forceinline__ long src_row(int r) {
    int b_ = r >> 8, n = r & 255;
    int bb = b_ >> 7, w_ = b_ & 127;
    int wt = w_ >> 6, wh = (w_ >> 3) & 7, ww = w_ & 7;
    int it = n >> 6, ih = (n >> 3) & 7, iw = n & 7;
    int t = (wt * 4 + it + 2) & 7;
    int h = (wh * 8 + ih + 4) & 63;
    int w = (ww * 8 + iw + 4) & 63;
    return (long)(((bb * TT + t) * HDIM + h) * WDIM + w);
}

// ---------------- CPB table ----------------
__global__ void cpb_kernel(const float* __restrict__ w1, const float* __restrict__ b1,
                           const float* __restrict__ w2, const float* __restrict__ ls) {
    int m = blockIdx.x;
    int tid = threadIdx.x;
    if (m == 0 && tid < HEADS)
        g_scale[tid] = expf(fminf(ls[tid], logf(100.0f)));

    int i = m / 225, rem = m % 225, j = rem / 15, k = rem % 15;
    float v0 = (float)(i - 3) * (8.0f / 3.0f);
    float v1 = (float)(j - 7) * (8.0f / 7.0f);
    float v2 = (float)(k - 7) * (8.0f / 7.0f);
    const float inv_l8 = 1.0f / log2f(8.0f);
    float c0 = copysignf(log2f(fabsf(v0) + 1.0f) * inv_l8, v0);
    float c1 = copysignf(log2f(fabsf(v1) + 1.0f) * inv_l8, v1);
    float c2 = copysignf(log2f(fabsf(v2) + 1.0f) * inv_l8, v2);

    float h = c0 * w1[tid * 3 + 0] + c1 * w1[tid * 3 + 1] + c2 * w1[tid * 3 + 2] + b1[tid];
    h = fmaxf(h, 0.0f);

    __shared__ float red[CPB_H];
    for (int hh = 0; hh < HEADS; hh++) {
        red[tid] = h * w2[hh * CPB_H + tid];
        __syncthreads();
        for (int s = CPB_H / 2; s > 0; s >>= 1) {
            if (tid < s) red[tid] += red[tid + s];
            __syncthreads();
        }
        if (tid == 0) {
            float t = red[0];
            g_tbl[m * HEADS + hh] = 16.0f / (1.0f + expf(-t));
        }
        __syncthreads();
    }
}

// ---------------- tf32 GEMM: 256x64 CTA, 4 warps x (64x64 warp tile), BK=8 ----------------
__device__ __forceinline__ uint32_t f2tf32(float f) {
    uint32_t u;
    asm("cvt.rna.tf32.f32 %0, %1;" : "=r"(u) : "f"(f));
    return u;
}

#define SKA 12   // smem k-stride (conflict-free: 12*grp mod 32 distinct)

template <int ACT, bool GATHER>
__device__ __forceinline__ void gemm_tc_body(const float* __restrict__ A, const float* __restrict__ Wt,
                                             const float* __restrict__ bias, float* __restrict__ Cm,
                                             int Nn, int K) {
    __shared__ uint32_t As[2][256][SKA];
    __shared__ uint32_t Bs[2][64][SKA];

    int tid = threadIdx.x;          // 0..127
    int lane = tid & 31;
    int warp = tid >> 5;            // 0..3 (M blocks of 64)
    int m0 = blockIdx.y * 256;
    int n0 = blockIdx.x * 64;

    int grp = lane >> 2;            // 0..7
    int kc  = lane & 3;             // 0..3

    // global->smem assignments: A: 4 float4/thread, B: 1 float4/thread
    int rA[4], qA[4];
    long abase[4];
    #pragma unroll
    for (int i = 0; i < 4; i++) {
        int e = tid + i * 128;
        rA[i] = e >> 1;
        qA[i] = (e & 1) * 4;
        abase[i] = GATHER ? src_row(m0 + rA[i]) * CC : (long)(m0 + rA[i]) * K;
    }
    int rB = tid >> 1, qB = (tid & 1) * 4;
    long bbase = (long)(n0 + rB) * K;

    float acc[4][8][4];
    #pragma unroll
    for (int i = 0; i < 4; i++)
        #pragma unroll
        for (int j = 0; j < 8; j++)
            #pragma unroll
            for (int q = 0; q < 4; q++) acc[i][j][q] = 0.0f;

    int nT = K / 8;
    float4 pa[4], pb;
    #pragma unroll
    for (int i = 0; i < 4; i++) pa[i] = *(const float4*)&A[abase[i] + qA[i]];
    pb = *(const float4*)&Wt[bbase + qB];

    // store stage 0
    #pragma unroll
    for (int i = 0; i < 4; i++) {
        As[0][rA[i]][qA[i] + 0] = f2tf32(pa[i].x);
        As[0][rA[i]][qA[i] + 1] = f2tf32(pa[i].y);
        As[0][rA[i]][qA[i] + 2] = f2tf32(pa[i].z);
        As[0][rA[i]][qA[i] + 3] = f2tf32(pa[i].w);
    }
    Bs[0][rB][qB + 0] = f2tf32(pb.x);
    Bs[0][rB][qB + 1] = f2tf32(pb.y);
    Bs[0][rB][qB + 2] = f2tf32(pb.z);
    Bs[0][rB][qB + 3] = f2tf32(pb.w);

    for (int k = 0; k < nT; k++) {
        if (k + 1 < nT) {
            int kn = (k + 1) * 8;
            #pragma unroll
            for (int i = 0; i < 4; i++) pa[i] = *(const float4*)&A[abase[i] + kn + qA[i]];
            pb = *(const float4*)&Wt[bbase + kn + qB];
        }
        __syncthreads();
        uint32_t (*as)[SKA] = As[k & 1];
        uint32_t (*bs)[SKA] = Bs[k & 1];

        uint32_t af[4][4];
        #pragma unroll
        for (int mt = 0; mt < 4; mt++) {
            int r = warp * 64 + mt * 16 + grp;
            af[mt][0] = as[r][kc];
            af[mt][1] = as[r + 8][kc];
            af[mt][2] = as[r][kc + 4];
            af[mt][3] = as[r + 8][kc + 4];
        }
        uint32_t bf[8][2];
        #pragma unroll
        for (int nt = 0; nt < 8; nt++) {
            int c = nt * 8 + grp;
            bf[nt][0] = bs[c][kc];
            bf[nt][1] = bs[c][kc + 4];
        }
        #pragma unroll
        for (int mt = 0; mt < 4; mt++)
            #pragma unroll
            for (int nt = 0; nt < 8; nt++) {
                asm volatile(
                    "mma.sync.aligned.m16n8k8.row.col.f32.tf32.tf32.f32 "
                    "{%0,%1,%2,%3}, {%4,%5,%6,%7}, {%8,%9}, {%0,%1,%2,%3};\n"
                    : "+f"(acc[mt][nt][0]), "+f"(acc[mt][nt][1]),
                      "+f"(acc[mt][nt][2]), "+f"(acc[mt][nt][3])
                    : "r"(af[mt][0]), "r"(af[mt][1]), "r"(af[mt][2]), "r"(af[mt][3]),
                      "r"(bf[nt][0]), "r"(bf[nt][1]));
            }

        if (k + 1 < nT) {
            uint32_t (*asn)[SKA] = As[(k + 1) & 1];
            uint32_t (*bsn)[SKA] = Bs[(k + 1) & 1];
            #pragma unroll
            for (int i = 0; i < 4; i++) {
                asn[rA[i]][qA[i] + 0] = f2tf32(pa[i].x);
                asn[rA[i]][qA[i] + 1] = f2tf32(pa[i].y);
                asn[rA[i]][qA[i] + 2] = f2tf32(pa[i].z);
                asn[rA[i]][qA[i] + 3] = f2tf32(pa[i].w);
            }
            bsn[rB][qB + 0] = f2tf32(pb.x);
            bsn[rB][qB + 1] = f2tf32(pb.y);
            bsn[rB][qB + 2] = f2tf32(pb.z);
            bsn[rB][qB + 3] = f2tf32(pb.w);
        }
    }

    #pragma unroll
    for (int mt = 0; mt < 4; mt++) {
        int row = m0 + warp * 64 + mt * 16 + grp;
        #pragma unroll
        for (int nt = 0; nt < 8; nt++) {
            int col = n0 + nt * 8 + kc * 2;
            float b0 = bias[col], b1 = bias[col + 1];
            float c0 = acc[mt][nt][0] + b0;
            float c1 = acc[mt][nt][1] + b1;
            float c2 = acc[mt][nt][2] + b0;
            float c3 = acc[mt][nt][3] + b1;
            if (ACT == 1) {
                c0 = 0.5f * c0 * (1.0f + erff(c0 * 0.70710678118654752f));
                c1 = 0.5f * c1 * (1.0f + erff(c1 * 0.70710678118654752f));
                c2 = 0.5f * c2 * (1.0f + erff(c2 * 0.70710678118654752f));
                c3 = 0.5f * c3 * (1.0f + erff(c3 * 0.70710678118654752f));
            }
            *(float2*)&Cm[(long)row * Nn + col] = make_float2(c0, c1);
            *(float2*)&Cm[(long)(row + 8) * Nn + col] = make_float2(c2, c3);
        }
    }
}

__global__ void __launch_bounds__(128) gemm_qkv_k (const float* X, const float* Wt, const float* b) { gemm_tc_body<0, true >(X,    Wt, b, g_qkv, 3 * CC, CC); }
__global__ void __launch_bounds__(128) gemm_proj_k(const float* Wt, const float* b)                 { gemm_tc_body<0, false>(g_xw, Wt, b, g_pr,  CC,     CC); }
__global__ void __launch_bounds__(128) gemm_fc1_k (const float* Wt, const float* b)                 { gemm_tc_body<1, false>(g_x1, Wt, b, g_h1,  HID,    CC); }
__global__ void __launch_bounds__(128) gemm_fc2_k (const float* Wt, const float* b)                 { gemm_tc_body<0, false>(g_h1, Wt, b, g_pr,  CC,    HID); }

// ---------------- windowed attention: fused q/k normalize, single pass, f32x2 ----------------
__global__ void __launch_bounds__(256) attn_kernel() {
    int b_ = blockIdx.x / HEADS;
    int hh = blockIdx.x % HEADS;
    int n = threadIdx.x;

    __shared__ __align__(16) double k_sh[128 * 16];
    __shared__ __align__(16) double v_sh[128 * 16];
    __shared__ float tbl_sh[CPB_M];
    __shared__ int   reg_sh[NTOK];
    __shared__ int   jidx_sh[NTOK];

    for (int i = n; i < CPB_M; i += 256) tbl_sh[i] = g_tbl[i * HEADS + hh];
    {
        int w_ = b_ & 127;
        int wt = w_ >> 6, wh = (w_ >> 3) & 7, ww = w_ & 7;
        int it = n >> 6, ih = (n >> 3) & 7, iw = n & 7;
        int ts = wt * 4 + it, hs = wh * 8 + ih, ws = ww * 8 + iw;
        int dt = (ts < 4) ? 0 : (ts < 6 ? 1 : 2);
        int dh = (hs < 56) ? 0 : (hs < 60 ? 1 : 2);
        int dw = (ws < 56) ? 0 : (ws < 60 ? 1 : 2);
        reg_sh[n] = dt * 9 + dh * 3 + dw;
        jidx_sh[n] = it * 225 + ih * 15 + iw;
    }
    __syncthreads();

    float scale_h = g_scale[hh];
    ull q2[16];
    {
        const float4* qp = (const float4*)&g_qkv[((long)b_ * NTOK + n) * (3 * CC) + hh * DH];
        float4 qv[8];
        float ss = 0.0f;
        #pragma unroll
        for (int f = 0; f < 8; f++) {
            qv[f] = qp[f];
            ss += qv[f].x * qv[f].x + qv[f].y * qv[f].y + qv[f].z * qv[f].z + qv[f].w * qv[f].w;
        }
        float rn = scale_h / fmaxf(sqrtf(ss), 1e-12f);
        #pragma unroll
        for (int f = 0; f < 8; f++) {
            q2[2 * f]     = packxy(qv[f].x * rn, qv[f].y * rn);
            q2[2 * f + 1] = packxy(qv[f].z * rn, qv[f].w * rn);
        }
    }
    int it = n >> 6, ih = (n >> 3) & 7, iw = n & 7;
    int myC = (it + 3) * 225 + (ih + 7) * 15 + (iw + 7);
    int myreg = reg_sh[n];
    float M = scale_h + 16.0f;

    float denom = 0.0f;
    ull out2[16];
    #pragma unroll
    for (int f = 0; f < 16; f++) out2[f] = 0ull;

    for (int t = 0; t < 2; t++) {
        __syncthreads();
        #pragma unroll
        for (int i = 0; i < 4; i++) {
            int e = i * 256 + n;
            int key = e >> 3, f2 = e & 7;
            long base = ((long)b_ * NTOK + t * 128 + key) * (3 * CC) + hh * DH + f2 * 4;
            float4 kd = *(const float4*)&g_qkv[base + CC];
            float ss = kd.x * kd.x + kd.y * kd.y + kd.z * kd.z + kd.w * kd.w;
            ss += __shfl_xor_sync(0xffffffffu, ss, 1);
            ss += __shfl_xor_sync(0xffffffffu, ss, 2);
            ss += __shfl_xor_sync(0xffffffffu, ss, 4);
            float rn = 1.0f / fmaxf(sqrtf(ss), 1e-12f);
            double2 kp;
            kp.x = __longlong_as_double(packxy(kd.x * rn, kd.y * rn));
            kp.y = __longlong_as_double(packxy(kd.z * rn, kd.w * rn));
            ((double2*)&k_sh[key * 16])[f2] = kp;
            ((double2*)&v_sh[key * 16])[f2] = *(const double2*)&g_qkv[base + 2 * CC];
        }
        __syncthreads();
        for (int ml = 0; ml < 128; ml++) {
            int m = t * 128 + ml;
            const double2* kp = (const double2*)&k_sh[ml * 16];
            ull acc = 0ull;
            #pragma unroll
            for (int f = 0; f < 8; f++) {
                double2 kd = kp[f];
                FMA2(acc, q2[2 * f],     __double_as_longlong(kd.x));
                FMA2(acc, q2[2 * f + 1], __double_as_longlong(kd.y));
            }
            float dot = __uint_as_float((unsigned)acc) + __uint_as_float((unsigned)(acc >> 32));
            float logit = dot + tbl_sh[myC - jidx_sh[m]]
                        + ((reg_sh[m] == myreg) ? 0.0f : -100.0f) - M;
            float w = __expf(logit);
            denom += w;
            ull w2 = pack2(w);
            const double2* vp = (const double2*)&v_sh[ml * 16];
            #pragma unroll
            for (int f = 0; f < 8; f++) {
                double2 vd = vp[f];
                FMA2(out2[2 * f],     w2, __double_as_longlong(vd.x));
                FMA2(out2[2 * f + 1], w2, __double_as_longlong(vd.y));
            }
        }
    }
    ull rd2 = pack2(1.0f / denom);
    double* orow = (double*)&g_xw[((long)b_ * NTOK + n) * CC + hh * DH];
    #pragma unroll
    for (int f = 0; f < 16; f++) {
        ull r;
        MUL2(r, out2[f], rd2);
        orow[f] = __longlong_as_double(r);
    }
}

// ---------------- LN(proj) + residual scatter ----------------
__global__ void attn_post_kernel(const float* __restrict__ x,
                                 const float* __restrict__ g, const float* __restrict__ b) {
    int r = blockIdx.x;
    int c = threadIdx.x;
    float v = g_pr[(long)r * CC + c];
    float s1 = v, s2 = v * v;
    #pragma unroll
    for (int o = 16; o; o >>= 1) {
        s1 += __shfl_xor_sync(0xffffffffu, s1, o);
        s2 += __shfl_xor_sync(0xffffffffu, s2, o);
    }
    __shared__ float p1[6], p2[6];
    int w = c >> 5;
    if ((c & 31) == 0) { p1[w] = s1; p2[w] = s2; }
    __syncthreads();
    s1 = p1[0] + p1[1] + p1[2] + p1[3] + p1[4] + p1[5];
    s2 = p2[0] + p2[1] + p2[2] + p2[3] + p2[4] + p2[5];
    float mean = s1 * (1.0f / CC);
    float var = s2 * (1.0f / CC) - mean * mean;
    float ln = (v - mean) * rsqrtf(var + 1e-5f) * g[c] + b[c];
    long dst = src_row(r) * CC + c;
    g_x1[dst] = x[dst] + ln;
}

// ---------------- final LN(fc2) + residual -> output ----------------
__global__ void final_kernel(float* __restrict__ out,
                             const float* __restrict__ g, const float* __restrict__ b) {
    int r = blockIdx.x;
    int c = threadIdx.x;
    float v = g_pr[(long)r * CC + c];
    float s1 = v, s2 = v * v;
    #pragma unroll
    for (int o = 16; o; o >>= 1) {
        s1 += __shfl_xor_sync(0xffffffffu, s1, o);
        s2 += __shfl_xor_sync(0xffffffffu, s2, o);
    }
    __shared__ float p1[6], p2[6];
    int w = c >> 5;
    if ((c & 31) == 0) { p1[w] = s1; p2[w] = s2; }
    __syncthreads();
    s1 = p1[0] + p1[1] + p1[2] + p1[3] + p1[4] + p1[5];
    s2 = p2[0] + p2[1] + p2[2] + p2[3] + p2[4] + p2[5];
    float mean = s1 * (1.0f / CC);
    float var = s2 * (1.0f / CC) - mean * mean;
    float ln = (v - mean) * rsqrtf(var + 1e-5f) * g[c] + b[c];
    out[(long)r * CC + c] = g_x1[(long)r * CC + c] + ln;
}

// ---------------- launch ----------------
extern "C" void kernel_launch(void* const* d_in, const int* in_sizes, int n_in,
                              void* d_out, int out_size) {
    const float* x      = (const float*)d_in[0];
    const float* qkv_w  = (const float*)d_in[1];
    const float* qkv_b  = (const float*)d_in[2];
    const float* proj_w = (const float*)d_in[3];
    const float* proj_b = (const float*)d_in[4];
    const float* cpb_w1 = (const float*)d_in[5];
    const float* cpb_b1 = (const float*)d_in[6];
    const float* cpb_w2 = (const float*)d_in[7];
    const float* ls     = (const float*)d_in[8];
    const float* n1g    = (const float*)d_in[9];
    const float* n1b    = (const float*)d_in[10];
    const float* n2g    = (const float*)d_in[11];
    const float* n2b    = (const float*)d_in[12];
    const float* fc1_w  = (const float*)d_in[13];
    const float* fc1_b  = (const float*)d_in[14];
    const float* fc2_w  = (const float*)d_in[15];
    const float* fc2_b  = (const float*)d_in[16];
    float* out = (float*)d_out;

    cpb_kernel<<<CPB_M, CPB_H>>>(cpb_w1, cpb_b1, cpb_w2, ls);
    gemm_qkv_k<<<dim3((3 * CC) / 64, MROWS / 256), 128>>>(x, qkv_w, qkv_b);
    attn_kernel<<<BWIN * HEADS, 256>>>();
    gemm_proj_k<<<dim3(CC / 64, MROWS / 256), 128>>>(proj_w, proj_b);
    attn_post_kernel<<<MROWS, 192>>>(x, n1g, n1b);
    gemm_fc1_k<<<dim3(HID / 64, MROWS / 256), 128>>>(fc1_w, fc1_b);
    gemm_fc2_k<<<dim3(CC / 64, MROWS / 256), 128>>>(fc2_w, fc2_b);
    final_kernel<<<MROWS, 192>>>(out, n2g, n2b);
}

// round 8
// speedup vs baseline: 1.3324x; 1.3324x over previous
#include <cuda_runtime.h>
#include <stdint.h>
#include <math.h>

// ---------------- problem constants ----------------
#define BQ     2
#define TT     8
#define HDIM   64
#define WDIM   64
#define CC     192
#define HEADS  6
#define DH     32
#define NTOK   256
#define NWIN   128
#define BWIN   256
#define MROWS  65536
#define HID    768
#define CPB_M  1575
#define CPB_H  512
#define L2E    1.4426950408889634f

typedef unsigned long long ull;

// ---------------- scratch ----------------
__device__ float g_xw [MROWS * CC];        // attention output (window layout)
__device__ float g_qkv[MROWS * 3 * CC];
__device__ float g_pr [MROWS * CC];
__device__ float g_x1 [MROWS * CC];
__device__ float g_h1 [MROWS * HID];
__device__ float g_tbl[CPB_M * HEADS];
__device__ float g_scale[HEADS];

__device__ __forceinline__ float ex2f(float x) {
    float r;
    asm("ex2.approx.f32 %0, %1;" : "=f"(r) : "f"(x));
    return r;
}

// window row -> source row in (B,T,H,W) layout
__device__ __forceinline__ long src_row(int r) {
    int b_ = r >> 8, n = r & 255;
    int bb = b_ >> 7, w_ = b_ & 127;
    int wt = w_ >> 6, wh = (w_ >> 3) & 7, ww = w_ & 7;
    int it = n >> 6, ih = (n >> 3) & 7, iw = n & 7;
    int t = (wt * 4 + it + 2) & 7;
    int h = (wh * 8 + ih + 4) & 63;
    int w = (ww * 8 + iw + 4) & 63;
    return (long)(((bb * TT + t) * HDIM + h) * WDIM + w);
}

// ---------------- CPB table ----------------
__global__ void cpb_kernel(const float* __restrict__ w1, const float* __restrict__ b1,
                           const float* __restrict__ w2, const float* __restrict__ ls) {
    int m = blockIdx.x;
    int tid = threadIdx.x;
    if (m == 0 && tid < HEADS)
        g_scale[tid] = expf(fminf(ls[tid], logf(100.0f)));

    int i = m / 225, rem = m % 225, j = rem / 15, k = rem % 15;
    float v0 = (float)(i - 3) * (8.0f / 3.0f);
    float v1 = (float)(j - 7) * (8.0f / 7.0f);
    float v2 = (float)(k - 7) * (8.0f / 7.0f);
    const float inv_l8 = 1.0f / log2f(8.0f);
    float c0 = copysignf(log2f(fabsf(v0) + 1.0f) * inv_l8, v0);
    float c1 = copysignf(log2f(fabsf(v1) + 1.0f) * inv_l8, v1);
    float c2 = copysignf(log2f(fabsf(v2) + 1.0f) * inv_l8, v2);

    float h = c0 * w1[tid * 3 + 0] + c1 * w1[tid * 3 + 1] + c2 * w1[tid * 3 + 2] + b1[tid];
    h = fmaxf(h, 0.0f);

    __shared__ float red[CPB_H];
    for (int hh = 0; hh < HEADS; hh++) {
        red[tid] = h * w2[hh * CPB_H + tid];
        __syncthreads();
        for (int s = CPB_H / 2; s > 0; s >>= 1) {
            if (tid < s) red[tid] += red[tid + s];
            __syncthreads();
        }
        if (tid == 0) {
            float t = red[0];
            g_tbl[m * HEADS + hh] = 16.0f / (1.0f + expf(-t));
        }
        __syncthreads();
    }
}

// ---------------- tf32 GEMM (R5 config: 128x64 CTA, 8 warps, 2-stage) ----------------
__device__ __forceinline__ uint32_t f2tf32(float f) {
    uint32_t u;
    asm("cvt.rna.tf32.f32 %0, %1;" : "=r"(u) : "f"(f));
    return u;
}

#define MMA_TF32(acc, af, bf)                                              \
    asm volatile(                                                          \
        "mma.sync.aligned.m16n8k8.row.col.f32.tf32.tf32.f32 "              \
        "{%0,%1,%2,%3}, {%4,%5,%6,%7}, {%8,%9}, {%0,%1,%2,%3};\n"          \
        : "+f"(acc[0]), "+f"(acc[1]), "+f"(acc[2]), "+f"(acc[3])           \
        : "r"(af[0]), "r"(af[1]), "r"(af[2]), "r"(af[3]),                  \
          "r"(bf[0]), "r"(bf[1]))

template <int ACT, bool GATHER>
__device__ __forceinline__ void gemm_tc_body(const float* __restrict__ A, const float* __restrict__ Wt,
                                             const float* __restrict__ bias, float* __restrict__ Cm,
                                             int Nn, int K) {
    __shared__ uint32_t As[2][128][20];
    __shared__ uint32_t Bs[2][64][20];

    int tid = threadIdx.x;
    int lane = tid & 31;
    int warp = tid >> 5;
    int wm = warp >> 1;
    int wn = warp & 1;
    int m0 = blockIdx.y * 128;
    int n0 = blockIdx.x * 64;

    int grp = lane >> 2;
    int kc  = lane & 3;

    int ra0 = tid >> 2, ka = (tid & 3) * 4;
    int ra1 = ra0 + 64;
    int rb  = tid >> 2;

    long abase0, abase1;
    if (GATHER) {
        abase0 = src_row(m0 + ra0) * CC;
        abase1 = src_row(m0 + ra1) * CC;
    } else {
        abase0 = (long)(m0 + ra0) * K;
        abase1 = (long)(m0 + ra1) * K;
    }
    long bbase = (long)(n0 + rb) * K;

    float acc[2][4][4];
    #pragma unroll
    for (int i = 0; i < 2; i++)
        #pragma unroll
        for (int j = 0; j < 4; j++)
            #pragma unroll
            for (int q = 0; q < 4; q++) acc[i][j][q] = 0.0f;

    int nT = K / 16;
    float4 pa0 = *(const float4*)&A[abase0 + ka];
    float4 pa1 = *(const float4*)&A[abase1 + ka];
    float4 pb  = *(const float4*)&Wt[bbase + ka];

    {
        uint32_t (*as)[20] = As[0];
        uint32_t (*bs)[20] = Bs[0];
        as[ra0][ka + 0] = f2tf32(pa0.x); as[ra0][ka + 1] = f2tf32(pa0.y);
        as[ra0][ka + 2] = f2tf32(pa0.z); as[ra0][ka + 3] = f2tf32(pa0.w);
        as[ra1][ka + 0] = f2tf32(pa1.x); as[ra1][ka + 1] = f2tf32(pa1.y);
        as[ra1][ka + 2] = f2tf32(pa1.z); as[ra1][ka + 3] = f2tf32(pa1.w);
        bs[rb][ka + 0] = f2tf32(pb.x); bs[rb][ka + 1] = f2tf32(pb.y);
        bs[rb][ka + 2] = f2tf32(pb.z); bs[rb][ka + 3] = f2tf32(pb.w);
    }

    for (int k = 0; k < nT; k++) {
        if (k + 1 < nT) {
            int kn = (k + 1) * 16;
            pa0 = *(const float4*)&A[abase0 + kn + ka];
            pa1 = *(const float4*)&A[abase1 + kn + ka];
            pb  = *(const float4*)&Wt[bbase + kn + ka];
        }
        __syncthreads();
        uint32_t (*as)[20] = As[k & 1];
        uint32_t (*bs)[20] = Bs[k & 1];

        #pragma unroll
        for (int ks = 0; ks < 2; ks++) {
            int kb = ks * 8 + kc;
            uint32_t af[2][4];
            #pragma unroll
            for (int mt = 0; mt < 2; mt++) {
                int r = wm * 32 + mt * 16 + grp;
                af[mt][0] = as[r][kb];
                af[mt][1] = as[r + 8][kb];
                af[mt][2] = as[r][kb + 4];
                af[mt][3] = as[r + 8][kb + 4];
            }
            uint32_t bf[4][2];
            #pragma unroll
            for (int nt = 0; nt < 4; nt++) {
                int c = wn * 32 + nt * 8 + grp;
                bf[nt][0] = bs[c][kb];
                bf[nt][1] = bs[c][kb + 4];
            }
            #pragma unroll
            for (int mt = 0; mt < 2; mt++)
                #pragma unroll
                for (int nt = 0; nt < 4; nt++)
                    MMA_TF32(acc[mt][nt], af[mt], bf[nt]);
        }

        if (k + 1 < nT) {
            uint32_t (*asn)[20] = As[(k + 1) & 1];
            uint32_t (*bsn)[20] = Bs[(k + 1) & 1];
            asn[ra0][ka + 0] = f2tf32(pa0.x); asn[ra0][ka + 1] = f2tf32(pa0.y);
            asn[ra0][ka + 2] = f2tf32(pa0.z); asn[ra0][ka + 3] = f2tf32(pa0.w);
            asn[ra1][ka + 0] = f2tf32(pa1.x); asn[ra1][ka + 1] = f2tf32(pa1.y);
            asn[ra1][ka + 2] = f2tf32(pa1.z); asn[ra1][ka + 3] = f2tf32(pa1.w);
            bsn[rb][ka + 0] = f2tf32(pb.x); bsn[rb][ka + 1] = f2tf32(pb.y);
            bsn[rb][ka + 2] = f2tf32(pb.z); bsn[rb][ka + 3] = f2tf32(pb.w);
        }
    }

    #pragma unroll
    for (int mt = 0; mt < 2; mt++) {
        int row = m0 + wm * 32 + mt * 16 + grp;
        #pragma unroll
        for (int nt = 0; nt < 4; nt++) {
            int col = n0 + wn * 32 + nt * 8 + kc * 2;
            float b0 = bias[col], b1 = bias[col + 1];
            float c0 = acc[mt][nt][0] + b0;
            float c1 = acc[mt][nt][1] + b1;
            float c2 = acc[mt][nt][2] + b0;
            float c3 = acc[mt][nt][3] + b1;
            if (ACT == 1) {
                c0 = 0.5f * c0 * (1.0f + erff(c0 * 0.70710678118654752f));
                c1 = 0.5f * c1 * (1.0f + erff(c1 * 0.70710678118654752f));
                c2 = 0.5f * c2 * (1.0f + erff(c2 * 0.70710678118654752f));
                c3 = 0.5f * c3 * (1.0f + erff(c3 * 0.70710678118654752f));
            }
            *(float2*)&Cm[(long)row * Nn + col] = make_float2(c0, c1);
            *(float2*)&Cm[(long)(row + 8) * Nn + col] = make_float2(c2, c3);
        }
    }
}

__global__ void __launch_bounds__(256) gemm_qkv_k (const float* X, const float* Wt, const float* b) { gemm_tc_body<0, true >(X,    Wt, b, g_qkv, 3 * CC, CC); }
__global__ void __launch_bounds__(256) gemm_proj_k(const float* Wt, const float* b)                 { gemm_tc_body<0, false>(g_xw, Wt, b, g_pr,  CC,     CC); }
__global__ void __launch_bounds__(256) gemm_fc1_k (const float* Wt, const float* b)                 { gemm_tc_body<1, false>(g_x1, Wt, b, g_h1,  HID,    CC); }
__global__ void __launch_bounds__(256) gemm_fc2_k (const float* Wt, const float* b)                 { gemm_tc_body<0, false>(g_h1, Wt, b, g_pr,  CC,    HID); }

// ---------------- tensor-core windowed attention ----------------
// smem layout (dynamic):
//   uint32 ks[256][36]      @ 0        (36864 B)  K, normalized, tf32
//   float  vs[32][260]      @ 36864    (33280 B)  V transposed [dh][key]
//   float  ps[8][32][34]    @ 70144    (34816 B)  per-warp Q stage / P tile
//   float  tblp[1576]       @ 104960   (6304 B)   (tbl - M)*log2e, + sentinel
//   uint   jr[256]          @ 111264   (1024 B)   jidx | region<<20
//   uint   cjr[256]         @ 112288   (1024 B)   myC  | region<<20
#define ATTN_SMEM 113312

__global__ void __launch_bounds__(256, 2) attn_kernel() {
    extern __shared__ char smraw[];
    uint32_t* ks  = (uint32_t*)smraw;
    float*    vs  = (float*)(smraw + 36864);
    float*    ps  = (float*)(smraw + 70144);
    float*    tblp = (float*)(smraw + 104960);
    uint32_t* jrs = (uint32_t*)(smraw + 111264);
    uint32_t* cjrs = (uint32_t*)(smraw + 112288);

    int b_ = blockIdx.x / HEADS;
    int hh = blockIdx.x % HEADS;
    int tid = threadIdx.x;
    int lane = tid & 31;
    int wid = tid >> 5;
    int grp = lane >> 2, kc = lane & 3;

    float scale_h = g_scale[hh];
    float Mh = scale_h + 16.0f;   // logit upper bound (cos*scale + 16*sigmoid)

    // table (pre-scaled by log2e, max folded in) + sentinel
    for (int i = tid; i < CPB_M; i += 256)
        tblp[i] = g_tbl[i * HEADS + hh] * L2E - Mh * L2E;
    if (tid == 0) tblp[CPB_M] = -1000.0f;

    // per-token jidx/region words
    {
        int n = tid;
        int w_ = b_ & 127;
        int wt = w_ >> 6, wh = (w_ >> 3) & 7, ww = w_ & 7;
        int it = n >> 6, ih = (n >> 3) & 7, iw = n & 7;
        int ts = wt * 4 + it, hs = wh * 8 + ih, wv = ww * 8 + iw;
        int dt = (ts < 4) ? 0 : (ts < 6 ? 1 : 2);
        int dh = (hs < 56) ? 0 : (hs < 60 ? 1 : 2);
        int dw = (wv < 56) ? 0 : (wv < 60 ? 1 : 2);
        uint32_t reg = (uint32_t)(dt * 9 + dh * 3 + dw);
        jrs[n]  = (uint32_t)(it * 225 + ih * 15 + iw) | (reg << 20);
        cjrs[n] = (uint32_t)((it + 3) * 225 + (ih + 7) * 15 + (iw + 7)) | (reg << 20);
    }

    // K (normalize -> tf32) and V (transpose) into smem; one key per thread
    {
        int key = tid;
        long base = ((long)b_ * NTOK + key) * (3 * CC) + hh * DH;
        const float4* kp4 = (const float4*)&g_qkv[base + CC];
        const float4* vp4 = (const float4*)&g_qkv[base + 2 * CC];
        float4 kv[8];
        float ss = 0.0f;
        #pragma unroll
        for (int f = 0; f < 8; f++) {
            kv[f] = kp4[f];
            ss += kv[f].x * kv[f].x + kv[f].y * kv[f].y + kv[f].z * kv[f].z + kv[f].w * kv[f].w;
        }
        float rn = 1.0f / fmaxf(sqrtf(ss), 1e-12f);
        #pragma unroll
        for (int f = 0; f < 8; f++) {
            ks[key * 36 + f * 4 + 0] = f2tf32(kv[f].x * rn);
            ks[key * 36 + f * 4 + 1] = f2tf32(kv[f].y * rn);
            ks[key * 36 + f * 4 + 2] = f2tf32(kv[f].z * rn);
            ks[key * 36 + f * 4 + 3] = f2tf32(kv[f].w * rn);
        }
        #pragma unroll
        for (int f = 0; f < 8; f++) {
            float4 v = vp4[f];
            vs[(f * 4 + 0) * 260 + key] = v.x;
            vs[(f * 4 + 1) * 260 + key] = v.y;
            vs[(f * 4 + 2) * 260 + key] = v.z;
            vs[(f * 4 + 3) * 260 + key] = v.w;
        }
    }
    __syncthreads();

    // Q prep: one row per lane, normalize (scale folded), stage, extract A-frags
    float* myps = ps + wid * (32 * 34);
    {
        long qb = ((long)b_ * NTOK + wid * 32 + lane) * (3 * CC) + hh * DH;
        const float4* qp4 = (const float4*)&g_qkv[qb];
        float4 qv[8];
        float ss = 0.0f;
        #pragma unroll
        for (int f = 0; f < 8; f++) {
            qv[f] = qp4[f];
            ss += qv[f].x * qv[f].x + qv[f].y * qv[f].y + qv[f].z * qv[f].z + qv[f].w * qv[f].w;
        }
        float rn = scale_h / fmaxf(sqrtf(ss), 1e-12f);
        #pragma unroll
        for (int f = 0; f < 8; f++) {
            myps[lane * 34 + f * 4 + 0] = qv[f].x * rn;
            myps[lane * 34 + f * 4 + 1] = qv[f].y * rn;
            myps[lane * 34 + f * 4 + 2] = qv[f].z * rn;
            myps[lane * 34 + f * 4 + 3] = qv[f].w * rn;
        }
    }
    __syncwarp();
    uint32_t qa[2][4][4];
    #pragma unroll
    for (int mt = 0; mt < 2; mt++)
        #pragma unroll
        for (int kt = 0; kt < 4; kt++) {
            int r0 = mt * 16 + grp, c0 = kt * 8 + kc;
            qa[mt][kt][0] = f2tf32(myps[r0 * 34 + c0]);
            qa[mt][kt][1] = f2tf32(myps[(r0 + 8) * 34 + c0]);
            qa[mt][kt][2] = f2tf32(myps[r0 * 34 + c0 + 4]);
            qa[mt][kt][3] = f2tf32(myps[(r0 + 8) * 34 + c0 + 4]);
        }
    __syncwarp();

    uint32_t mycjr[4];
    #pragma unroll
    for (int i = 0; i < 4; i++)
        mycjr[i] = cjrs[wid * 32 + ((i >> 1) * 16 + (i & 1) * 8 + grp)];

    float denom[4] = {0.0f, 0.0f, 0.0f, 0.0f};
    float oacc[2][4][4];
    #pragma unroll
    for (int mt = 0; mt < 2; mt++)
        #pragma unroll
        for (int nt = 0; nt < 4; nt++)
            #pragma unroll
            for (int q = 0; q < 4; q++) oacc[mt][nt][q] = 0.0f;

    for (int ch = 0; ch < 8; ch++) {
        int n0 = ch * 32;
        // ---- S = Qn Kn^T (32 q x 32 keys) ----
        float s[2][4][4];
        #pragma unroll
        for (int mt = 0; mt < 2; mt++)
            #pragma unroll
            for (int nt = 0; nt < 4; nt++)
                #pragma unroll
                for (int q = 0; q < 4; q++) s[mt][nt][q] = 0.0f;
        #pragma unroll
        for (int kt = 0; kt < 4; kt++) {
            uint32_t kb[4][2];
            #pragma unroll
            for (int nt = 0; nt < 4; nt++) {
                int krow = n0 + nt * 8 + grp;
                kb[nt][0] = ks[krow * 36 + kt * 8 + kc];
                kb[nt][1] = ks[krow * 36 + kt * 8 + kc + 4];
            }
            #pragma unroll
            for (int mt = 0; mt < 2; mt++)
                #pragma unroll
                for (int nt = 0; nt < 4; nt++)
                    MMA_TF32(s[mt][nt], qa[mt][kt], kb[nt]);
        }
        // ---- epilogue: bias + mask + exp -> P (to smem) + rowsum ----
        #pragma unroll
        for (int nt = 0; nt < 4; nt++) {
            int k0 = n0 + nt * 8 + 2 * kc;
            uint32_t jr0 = jrs[k0], jr1 = jrs[k0 + 1];
            #pragma unroll
            for (int mt = 0; mt < 2; mt++)
                #pragma unroll
                for (int h = 0; h < 2; h++) {
                    uint32_t mj = mycjr[mt * 2 + h];
                    uint32_t d0 = mj - jr0, x0 = mj ^ jr0;
                    uint32_t d1 = mj - jr1, x1 = mj ^ jr1;
                    int i0 = (x0 < (1u << 20)) ? (int)(d0 & 0xFFFFFu) : CPB_M;
                    int i1 = (x1 < (1u << 20)) ? (int)(d1 & 0xFFFFFu) : CPB_M;
                    float p0 = ex2f(s[mt][nt][h * 2 + 0] * L2E + tblp[i0]);
                    float p1 = ex2f(s[mt][nt][h * 2 + 1] * L2E + tblp[i1]);
                    denom[mt * 2 + h] += p0 + p1;
                    int row = mt * 16 + h * 8 + grp;
                    *(float2*)&myps[row * 34 + nt * 8 + 2 * kc] = make_float2(p0, p1);
                }
        }
        __syncwarp();
        // ---- O += P V (raw f32 bits as tf32 operands: HW truncates) ----
        #pragma unroll
        for (int kt = 0; kt < 4; kt++) {
            uint32_t pa[2][4], vb[4][2];
            #pragma unroll
            for (int mt = 0; mt < 2; mt++) {
                int r0 = mt * 16 + grp, c0 = kt * 8 + kc;
                pa[mt][0] = __float_as_uint(myps[r0 * 34 + c0]);
                pa[mt][1] = __float_as_uint(myps[(r0 + 8) * 34 + c0]);
                pa[mt][2] = __float_as_uint(myps[r0 * 34 + c0 + 4]);
                pa[mt][3] = __float_as_uint(myps[(r0 + 8) * 34 + c0 + 4]);
            }
            #pragma unroll
            for (int nt = 0; nt < 4; nt++) {
                vb[nt][0] = __float_as_uint(vs[(nt * 8 + grp) * 260 + n0 + kt * 8 + kc]);
                vb[nt][1] = __float_as_uint(vs[(nt * 8 + grp) * 260 + n0 + kt * 8 + kc + 4]);
            }
            #pragma unroll
            for (int mt = 0; mt < 2; mt++)
                #pragma unroll
                for (int nt = 0; nt < 4; nt++)
                    MMA_TF32(oacc[mt][nt], pa[mt], vb[nt]);
        }
        __syncwarp();
    }

    // finalize: reduce denoms across the 4 kc-lanes sharing each row, scale, store
    #pragma unroll
    for (int i = 0; i < 4; i++) {
        denom[i] += __shfl_xor_sync(0xffffffffu, denom[i], 1);
        denom[i] += __shfl_xor_sync(0xffffffffu, denom[i], 2);
        denom[i] = 1.0f / denom[i];
    }
    long ob = ((long)b_ * NTOK + wid * 32) * CC + hh * DH;
    #pragma unroll
    for (int mt = 0; mt < 2; mt++)
        #pragma unroll
        for (int nt = 0; nt < 4; nt++) {
            int r0 = mt * 16 + grp, c0 = nt * 8 + 2 * kc;
            float rd0 = denom[mt * 2 + 0], rd1 = denom[mt * 2 + 1];
            *(float2*)&g_xw[ob + (long)r0 * CC + c0] =
                make_float2(oacc[mt][nt][0] * rd0, oacc[mt][nt][1] * rd0);
            *(float2*)&g_xw[ob + (long)(r0 + 8) * CC + c0] =
                make_float2(oacc[mt][nt][2] * rd1, oacc[mt][nt][3] * rd1);
        }
}

// ---------------- LN(proj) + residual scatter ----------------
__global__ void attn_post_kernel(const float* __restrict__ x,
                                 const float* __restrict__ g, const float* __restrict__ b) {
    int r = blockIdx.x;
    int c = threadIdx.x;
    float v = g_pr[(long)r * CC + c];
    float s1 = v, s2 = v * v;
    #pragma unroll
    for (int o = 16; o; o >>= 1) {
        s1 += __shfl_xor_sync(0xffffffffu, s1, o);
        s2 += __shfl_xor_sync(0xffffffffu, s2, o);
    }
    __shared__ float p1[6], p2[6];
    int w = c >> 5;
    if ((c & 31) == 0) { p1[w] = s1; p2[w] = s2; }
    __syncthreads();
    s1 = p1[0] + p1[1] + p1[2] + p1[3] + p1[4] + p1[5];
    s2 = p2[0] + p2[1] + p2[2] + p2[3] + p2[4] + p2[5];
    float mean = s1 * (1.0f / CC);
    float var = s2 * (1.0f / CC) - mean * mean;
    float ln = (v - mean) * rsqrtf(var + 1e-5f) * g[c] + b[c];
    long dst = src_row(r) * CC + c;
    g_x1[dst] = x[dst] + ln;
}

// ---------------- final LN(fc2) + residual -> output ----------------
__global__ void final_kernel(float* __restrict__ out,
                             const float* __restrict__ g, const float* __restrict__ b) {
    int r = blockIdx.x;
    int c = threadIdx.x;
    float v = g_pr[(long)r * CC + c];
    float s1 = v, s2 = v * v;
    #pragma unroll
    for (int o = 16; o; o >>= 1) {
        s1 += __shfl_xor_sync(0xffffffffu, s1, o);
        s2 += __shfl_xor_sync(0xffffffffu, s2, o);
    }
    __shared__ float p1[6], p2[6];
    int w = c >> 5;
    if ((c & 31) == 0) { p1[w] = s1; p2[w] = s2; }
    __syncthreads();
    s1 = p1[0] + p1[1] + p1[2] + p1[3] + p1[4] + p1[5];
    s2 = p2[0] + p2[1] + p2[2] + p2[3] + p2[4] + p2[5];
    float mean = s1 * (1.0f / CC);
    float var = s2 * (1.0f / CC) - mean * mean;
    float ln = (v - mean) * rsqrtf(var + 1e-5f) * g[c] + b[c];
    out[(long)r * CC + c] = g_x1[(long)r * CC + c] + ln;
}

// ---------------- launch ----------------
extern "C" void kernel_launch(void* const* d_in, const int* in_sizes, int n_in,
                              void* d_out, int out_size) {
    const float* x      = (const float*)d_in[0];
    const float* qkv_w  = (const float*)d_in[1];
    const float* qkv_b  = (const float*)d_in[2];
    const float* proj_w = (const float*)d_in[3];
    const float* proj_b = (const float*)d_in[4];
    const float* cpb_w1 = (const float*)d_in[5];
    const float* cpb_b1 = (const float*)d_in[6];
    const float* cpb_w2 = (const float*)d_in[7];
    const float* ls     = (const float*)d_in[8];
    const float* n1g    = (const float*)d_in[9];
    const float* n1b    = (const float*)d_in[10];
    const float* n2g    = (const float*)d_in[11];
    const float* n2b    = (const float*)d_in[12];
    const float* fc1_w  = (const float*)d_in[13];
    const float* fc1_b  = (const float*)d_in[14];
    const float* fc2_w  = (const float*)d_in[15];
    const float* fc2_b  = (const float*)d_in[16];
    float* out = (float*)d_out;

    cudaFuncSetAttribute(attn_kernel, cudaFuncAttributeMaxDynamicSharedMemorySize, ATTN_SMEM);

    cpb_kernel<<<CPB_M, CPB_H>>>(cpb_w1, cpb_b1, cpb_w2, ls);
    gemm_qkv_k<<<dim3((3 * CC) / 64, MROWS / 128), 256>>>(x, qkv_w, qkv_b);
    attn_kernel<<<BWIN * HEADS, 256, ATTN_SMEM>>>();
    gemm_proj_k<<<dim3(CC / 64, MROWS / 128), 256>>>(proj_w, proj_b);
    attn_post_kernel<<<MROWS, 192>>>(x, n1g, n1b);
    gemm_fc1_k<<<dim3(HID / 64, MROWS / 128), 256>>>(fc1_w, fc1_b);
    gemm_fc2_k<<<dim3(CC / 64, MROWS / 128), 256>>>(fc2_w, fc2_b);
    final_kernel<<<MROWS, 192>>>(out, n2g, n2b);
}

// round 9
// speedup vs baseline: 1.4222x; 1.0674x over previous
#include <cuda_runtime.h>
#include <stdint.h>
#include <math.h>

// ---------------- problem constants ----------------
#define BQ     2
#define TT     8
#define HDIM   64
#define WDIM   64
#define CC     192
#define HEADS  6
#define DH     32
#define NTOK   256
#define NWIN   128
#define BWIN   256
#define MROWS  65536
#define HID    768
#define CPB_M  1575
#define CPB_H  512
#define L2E    1.4426950408889634f

typedef unsigned long long ull;

// ---------------- scratch ----------------
__device__ float g_xw [MROWS * CC];        // attention output (window layout)
__device__ float g_qkv[MROWS * 3 * CC];
__device__ float g_pr [MROWS * CC];
__device__ float g_x1 [MROWS * CC];
__device__ float g_h1 [MROWS * HID];
__device__ float g_tbl[CPB_M * HEADS];
__device__ float g_scale[HEADS];

__device__ __forceinline__ float ex2f(float x) {
    float r;
    asm("ex2.approx.f32 %0, %1;" : "=f"(r) : "f"(x));
    return r;
}

// window row -> source row in (B,T,H,W) layout
__device__ __forceinline__ long src_row(int r) {
    int b_ = r >> 8, n = r & 255;
    int bb = b_ >> 7, w_ = b_ & 127;
    int wt = w_ >> 6, wh = (w_ >> 3) & 7, ww = w_ & 7;
    int it = n >> 6, ih = (n >> 3) & 7, iw = n & 7;
    int t = (wt * 4 + it + 2) & 7;
    int h = (wh * 8 + ih + 4) & 63;
    int w = (ww * 8 + iw + 4) & 63;
    return (long)(((bb * TT + t) * HDIM + h) * WDIM + w);
}

// ---------------- CPB table ----------------
__global__ void cpb_kernel(const float* __restrict__ w1, const float* __restrict__ b1,
                           const float* __restrict__ w2, const float* __restrict__ ls) {
    int m = blockIdx.x;
    int tid = threadIdx.x;
    if (m == 0 && tid < HEADS)
        g_scale[tid] = expf(fminf(ls[tid], logf(100.0f)));

    int i = m / 225, rem = m % 225, j = rem / 15, k = rem % 15;
    float v0 = (float)(i - 3) * (8.0f / 3.0f);
    float v1 = (float)(j - 7) * (8.0f / 7.0f);
    float v2 = (float)(k - 7) * (8.0f / 7.0f);
    const float inv_l8 = 1.0f / log2f(8.0f);
    float c0 = copysignf(log2f(fabsf(v0) + 1.0f) * inv_l8, v0);
    float c1 = copysignf(log2f(fabsf(v1) + 1.0f) * inv_l8, v1);
    float c2 = copysignf(log2f(fabsf(v2) + 1.0f) * inv_l8, v2);

    float h = c0 * w1[tid * 3 + 0] + c1 * w1[tid * 3 + 1] + c2 * w1[tid * 3 + 2] + b1[tid];
    h = fmaxf(h, 0.0f);

    __shared__ float red[CPB_H];
    for (int hh = 0; hh < HEADS; hh++) {
        red[tid] = h * w2[hh * CPB_H + tid];
        __syncthreads();
        for (int s = CPB_H / 2; s > 0; s >>= 1) {
            if (tid < s) red[tid] += red[tid + s];
            __syncthreads();
        }
        if (tid == 0) {
            float t = red[0];
            g_tbl[m * HEADS + hh] = 16.0f / (1.0f + expf(-t));
        }
        __syncthreads();
    }
}

// ---------------- tf32 GEMM: 256x64 CTA, 8 warps x (64x32 warp tile), BK=16, 2-stage ----------------
__device__ __forceinline__ uint32_t f2tf32(float f) {
    uint32_t u;
    asm("cvt.rna.tf32.f32 %0, %1;" : "=r"(u) : "f"(f));
    return u;
}

#define MMA_TF32(acc, af, bf)                                              \
    asm volatile(                                                          \
        "mma.sync.aligned.m16n8k8.row.col.f32.tf32.tf32.f32 "              \
        "{%0,%1,%2,%3}, {%4,%5,%6,%7}, {%8,%9}, {%0,%1,%2,%3};\n"          \
        : "+f"(acc[0]), "+f"(acc[1]), "+f"(acc[2]), "+f"(acc[3])           \
        : "r"(af[0]), "r"(af[1]), "r"(af[2]), "r"(af[3]),                  \
          "r"(bf[0]), "r"(bf[1]))

#define GEMM_SMEM (2 * 256 * 20 * 4 + 2 * 64 * 20 * 4)   // 51200 B

template <int ACT, bool GATHER>
__device__ __forceinline__ void gemm_tc_body(const float* __restrict__ A, const float* __restrict__ Wt,
                                             const float* __restrict__ bias, float* __restrict__ Cm,
                                             int Nn, int K) {
    extern __shared__ uint32_t smem_u[];
    uint32_t (*As)[256][20] = (uint32_t (*)[256][20])smem_u;            // 2 stages
    uint32_t (*Bs)[64][20]  = (uint32_t (*)[64][20])(smem_u + 2 * 256 * 20);

    int tid = threadIdx.x;        // 0..255
    int lane = tid & 31;
    int warp = tid >> 5;          // 0..7
    int wm = warp >> 1;           // 0..3 -> M offset wm*64
    int wn = warp & 1;            // 0..1 -> N offset wn*32
    int m0 = blockIdx.y * 256;
    int n0 = blockIdx.x * 64;

    int grp = lane >> 2;          // 0..7
    int kc  = lane & 3;           // 0..3

    // global->smem: A 4 float4/thread, B 1 float4/thread
    int rA[4], qAo[4];
    long abase[4];
    #pragma unroll
    for (int i = 0; i < 4; i++) {
        int e = tid + i * 256;          // (row, quad)
        rA[i]  = e >> 2;
        qAo[i] = (e & 3) * 4;
        abase[i] = GATHER ? src_row(m0 + rA[i]) * CC : (long)(m0 + rA[i]) * K;
    }
    int rB = tid >> 2, qB = (tid & 3) * 4;
    long bbase = (long)(n0 + rB) * K;

    float acc[4][4][4];
    #pragma unroll
    for (int i = 0; i < 4; i++)
        #pragma unroll
        for (int j = 0; j < 4; j++)
            #pragma unroll
            for (int q = 0; q < 4; q++) acc[i][j][q] = 0.0f;

    int nT = K / 16;
    float4 pa[4], pb;
    #pragma unroll
    for (int i = 0; i < 4; i++) pa[i] = *(const float4*)&A[abase[i] + qAo[i]];
    pb = *(const float4*)&Wt[bbase + qB];

    // store stage 0
    #pragma unroll
    for (int i = 0; i < 4; i++) {
        As[0][rA[i]][qAo[i] + 0] = f2tf32(pa[i].x);
        As[0][rA[i]][qAo[i] + 1] = f2tf32(pa[i].y);
        As[0][rA[i]][qAo[i] + 2] = f2tf32(pa[i].z);
        As[0][rA[i]][qAo[i] + 3] = f2tf32(pa[i].w);
    }
    Bs[0][rB][qB + 0] = f2tf32(pb.x);
    Bs[0][rB][qB + 1] = f2tf32(pb.y);
    Bs[0][rB][qB + 2] = f2tf32(pb.z);
    Bs[0][rB][qB + 3] = f2tf32(pb.w);

    for (int k = 0; k < nT; k++) {
        if (k + 1 < nT) {
            int kn = (k + 1) * 16;
            #pragma unroll
            for (int i = 0; i < 4; i++) pa[i] = *(const float4*)&A[abase[i] + kn + qAo[i]];
            pb = *(const float4*)&Wt[bbase + kn + qB];
        }
        __syncthreads();
        uint32_t (*as)[20] = As[k & 1];
        uint32_t (*bs)[20] = Bs[k & 1];

        #pragma unroll
        for (int ks = 0; ks < 2; ks++) {
            int kb = ks * 8 + kc;
            uint32_t af[4][4];
            #pragma unroll
            for (int mt = 0; mt < 4; mt++) {
                int r = wm * 64 + mt * 16 + grp;
                af[mt][0] = as[r][kb];
                af[mt][1] = as[r + 8][kb];
                af[mt][2] = as[r][kb + 4];
                af[mt][3] = as[r + 8][kb + 4];
            }
            uint32_t bf[4][2];
            #pragma unroll
            for (int nt = 0; nt < 4; nt++) {
                int c = wn * 32 + nt * 8 + grp;
                bf[nt][0] = bs[c][kb];
                bf[nt][1] = bs[c][kb + 4];
            }
            #pragma unroll
            for (int mt = 0; mt < 4; mt++)
                #pragma unroll
                for (int nt = 0; nt < 4; nt++)
                    MMA_TF32(acc[mt][nt], af[mt], bf[nt]);
        }

        if (k + 1 < nT) {
            uint32_t (*asn)[20] = As[(k + 1) & 1];
            uint32_t (*bsn)[20] = Bs[(k + 1) & 1];
            #pragma unroll
            for (int i = 0; i < 4; i++) {
                asn[rA[i]][qAo[i] + 0] = f2tf32(pa[i].x);
                asn[rA[i]][qAo[i] + 1] = f2tf32(pa[i].y);
                asn[rA[i]][qAo[i] + 2] = f2tf32(pa[i].z);
                asn[rA[i]][qAo[i] + 3] = f2tf32(pa[i].w);
            }
            bsn[rB][qB + 0] = f2tf32(pb.x);
            bsn[rB][qB + 1] = f2tf32(pb.y);
            bsn[rB][qB + 2] = f2tf32(pb.z);
            bsn[rB][qB + 3] = f2tf32(pb.w);
        }
    }

    #pragma unroll
    for (int mt = 0; mt < 4; mt++) {
        int row = m0 + wm * 64 + mt * 16 + grp;
        #pragma unroll
        for (int nt = 0; nt < 4; nt++) {
            int col = n0 + wn * 32 + nt * 8 + kc * 2;
            float b0 = bias[col], b1 = bias[col + 1];
            float c0 = acc[mt][nt][0] + b0;
            float c1 = acc[mt][nt][1] + b1;
            float c2 = acc[mt][nt][2] + b0;
            float c3 = acc[mt][nt][3] + b1;
            if (ACT == 1) {
                c0 = 0.5f * c0 * (1.0f + erff(c0 * 0.70710678118654752f));
                c1 = 0.5f * c1 * (1.0f + erff(c1 * 0.70710678118654752f));
                c2 = 0.5f * c2 * (1.0f + erff(c2 * 0.70710678118654752f));
                c3 = 0.5f * c3 * (1.0f + erff(c3 * 0.70710678118654752f));
            }
            *(float2*)&Cm[(long)row * Nn + col] = make_float2(c0, c1);
            *(float2*)&Cm[(long)(row + 8) * Nn + col] = make_float2(c2, c3);
        }
    }
}

__global__ void __launch_bounds__(256, 2) gemm_qkv_k (const float* X, const float* Wt, const float* b) { gemm_tc_body<0, true >(X,    Wt, b, g_qkv, 3 * CC, CC); }
__global__ void __launch_bounds__(256, 2) gemm_proj_k(const float* Wt, const float* b)                 { gemm_tc_body<0, false>(g_xw, Wt, b, g_pr,  CC,     CC); }
__global__ void __launch_bounds__(256, 2) gemm_fc1_k (const float* Wt, const float* b)                 { gemm_tc_body<1, false>(g_x1, Wt, b, g_h1,  HID,    CC); }
__global__ void __launch_bounds__(256, 2) gemm_fc2_k (const float* Wt, const float* b)                 { gemm_tc_body<0, false>(g_h1, Wt, b, g_pr,  CC,    HID); }

// ---------------- tensor-core windowed attention (unchanged from R8) ----------------
#define ATTN_SMEM 113312

__global__ void __launch_bounds__(256, 2) attn_kernel() {
    extern __shared__ char smraw[];
    uint32_t* ks  = (uint32_t*)smraw;
    float*    vs  = (float*)(smraw + 36864);
    float*    ps  = (float*)(smraw + 70144);
    float*    tblp = (float*)(smraw + 104960);
    uint32_t* jrs = (uint32_t*)(smraw + 111264);
    uint32_t* cjrs = (uint32_t*)(smraw + 112288);

    int b_ = blockIdx.x / HEADS;
    int hh = blockIdx.x % HEADS;
    int tid = threadIdx.x;
    int lane = tid & 31;
    int wid = tid >> 5;
    int grp = lane >> 2, kc = lane & 3;

    float scale_h = g_scale[hh];
    float Mh = scale_h + 16.0f;

    for (int i = tid; i < CPB_M; i += 256)
        tblp[i] = g_tbl[i * HEADS + hh] * L2E - Mh * L2E;
    if (tid == 0) tblp[CPB_M] = -1000.0f;

    {
        int n = tid;
        int w_ = b_ & 127;
        int wt = w_ >> 6, wh = (w_ >> 3) & 7, ww = w_ & 7;
        int it = n >> 6, ih = (n >> 3) & 7, iw = n & 7;
        int ts = wt * 4 + it, hs = wh * 8 + ih, wv = ww * 8 + iw;
        int dt = (ts < 4) ? 0 : (ts < 6 ? 1 : 2);
        int dh = (hs < 56) ? 0 : (hs < 60 ? 1 : 2);
        int dw = (wv < 56) ? 0 : (wv < 60 ? 1 : 2);
        uint32_t reg = (uint32_t)(dt * 9 + dh * 3 + dw);
        jrs[n]  = (uint32_t)(it * 225 + ih * 15 + iw) | (reg << 20);
        cjrs[n] = (uint32_t)((it + 3) * 225 + (ih + 7) * 15 + (iw + 7)) | (reg << 20);
    }

    {
        int key = tid;
        long base = ((long)b_ * NTOK + key) * (3 * CC) + hh * DH;
        const float4* kp4 = (const float4*)&g_qkv[base + CC];
        const float4* vp4 = (const float4*)&g_qkv[base + 2 * CC];
        float4 kv[8];
        float ss = 0.0f;
        #pragma unroll
        for (int f = 0; f < 8; f++) {
            kv[f] = kp4[f];
            ss += kv[f].x * kv[f].x + kv[f].y * kv[f].y + kv[f].z * kv[f].z + kv[f].w * kv[f].w;
        }
        float rn = 1.0f / fmaxf(sqrtf(ss), 1e-12f);
        #pragma unroll
        for (int f = 0; f < 8; f++) {
            ks[key * 36 + f * 4 + 0] = f2tf32(kv[f].x * rn);
            ks[key * 36 + f * 4 + 1] = f2tf32(kv[f].y * rn);
            ks[key * 36 + f * 4 + 2] = f2tf32(kv[f].z * rn);
            ks[key * 36 + f * 4 + 3] = f2tf32(kv[f].w * rn);
        }
        #pragma unroll
        for (int f = 0; f < 8; f++) {
            float4 v = vp4[f];
            vs[(f * 4 + 0) * 260 + key] = v.x;
            vs[(f * 4 + 1) * 260 + key] = v.y;
            vs[(f * 4 + 2) * 260 + key] = v.z;
            vs[(f * 4 + 3) * 260 + key] = v.w;
        }
    }
    __syncthreads();

    float* myps = ps + wid * (32 * 34);
    {
        long qb = ((long)b_ * NTOK + wid * 32 + lane) * (3 * CC) + hh * DH;
        const float4* qp4 = (const float4*)&g_qkv[qb];
        float4 qv[8];
        float ss = 0.0f;
        #pragma unroll
        for (int f = 0; f < 8; f++) {
            qv[f] = qp4[f];
            ss += qv[f].x * qv[f].x + qv[f].y * qv[f].y + qv[f].z * qv[f].z + qv[f].w * qv[f].w;
        }
        float rn = scale_h / fmaxf(sqrtf(ss), 1e-12f);
        #pragma unroll
        for (int f = 0; f < 8; f++) {
            myps[lane * 34 + f * 4 + 0] = qv[f].x * rn;
            myps[lane * 34 + f * 4 + 1] = qv[f].y * rn;
            myps[lane * 34 + f * 4 + 2] = qv[f].z * rn;
            myps[lane * 34 + f * 4 + 3] = qv[f].w * rn;
        }
    }
    __syncwarp();
    uint32_t qa[2][4][4];
    #pragma unroll
    for (int mt = 0; mt < 2; mt++)
        #pragma unroll
        for (int kt = 0; kt < 4; kt++) {
            int r0 = mt * 16 + grp, c0 = kt * 8 + kc;
            qa[mt][kt][0] = f2tf32(myps[r0 * 34 + c0]);
            qa[mt][kt][1] = f2tf32(myps[(r0 + 8) * 34 + c0]);
            qa[mt][kt][2] = f2tf32(myps[r0 * 34 + c0 + 4]);
            qa[mt][kt][3] = f2tf32(myps[(r0 + 8) * 34 + c0 + 4]);
        }
    __syncwarp();

    uint32_t mycjr[4];
    #pragma unroll
    for (int i = 0; i < 4; i++)
        mycjr[i] = cjrs[wid * 32 + ((i >> 1) * 16 + (i & 1) * 8 + grp)];

    float denom[4] = {0.0f, 0.0f, 0.0f, 0.0f};
    float oacc[2][4][4];
    #pragma unroll
    for (int mt = 0; mt < 2; mt++)
        #pragma unroll
        for (int nt = 0; nt < 4; nt++)
            #pragma unroll
            for (int q = 0; q < 4; q++) oacc[mt][nt][q] = 0.0f;

    for (int ch = 0; ch < 8; ch++) {
        int n0 = ch * 32;
        float s[2][4][4];
        #pragma unroll
        for (int mt = 0; mt < 2; mt++)
            #pragma unroll
            for (int nt = 0; nt < 4; nt++)
                #pragma unroll
                for (int q = 0; q < 4; q++) s[mt][nt][q] = 0.0f;
        #pragma unroll
        for (int kt = 0; kt < 4; kt++) {
            uint32_t kb[4][2];
            #pragma unroll
            for (int nt = 0; nt < 4; nt++) {
                int krow = n0 + nt * 8 + grp;
                kb[nt][0] = ks[krow * 36 + kt * 8 + kc];
                kb[nt][1] = ks[krow * 36 + kt * 8 + kc + 4];
            }
            #pragma unroll
            for (int mt = 0; mt < 2; mt++)
                #pragma unroll
                for (int nt = 0; nt < 4; nt++)
                    MMA_TF32(s[mt][nt], qa[mt][kt], kb[nt]);
        }
        #pragma unroll
        for (int nt = 0; nt < 4; nt++) {
            int k0 = n0 + nt * 8 + 2 * kc;
            uint32_t jr0 = jrs[k0], jr1 = jrs[k0 + 1];
            #pragma unroll
            for (int mt = 0; mt < 2; mt++)
                #pragma unroll
                for (int h = 0; h < 2; h++) {
                    uint32_t mj = mycjr[mt * 2 + h];
                    uint32_t d0 = mj - jr0, x0 = mj ^ jr0;
                    uint32_t d1 = mj - jr1, x1 = mj ^ jr1;
                    int i0 = (x0 < (1u << 20)) ? (int)(d0 & 0xFFFFFu) : CPB_M;
                    int i1 = (x1 < (1u << 20)) ? (int)(d1 & 0xFFFFFu) : CPB_M;
                    float p0 = ex2f(s[mt][nt][h * 2 + 0] * L2E + tblp[i0]);
                    float p1 = ex2f(s[mt][nt][h * 2 + 1] * L2E + tblp[i1]);
                    denom[mt * 2 + h] += p0 + p1;
                    int row = mt * 16 + h * 8 + grp;
                    *(float2*)&myps[row * 34 + nt * 8 + 2 * kc] = make_float2(p0, p1);
                }
        }
        __syncwarp();
        #pragma unroll
        for (int kt = 0; kt < 4; kt++) {
            uint32_t pa[2][4], vb[4][2];
            #pragma unroll
            for (int mt = 0; mt < 2; mt++) {
                int r0 = mt * 16 + grp, c0 = kt * 8 + kc;
                pa[mt][0] = __float_as_uint(myps[r0 * 34 + c0]);
                pa[mt][1] = __float_as_uint(myps[(r0 + 8) * 34 + c0]);
                pa[mt][2] = __float_as_uint(myps[r0 * 34 + c0 + 4]);
                pa[mt][3] = __float_as_uint(myps[(r0 + 8) * 34 + c0 + 4]);
            }
            #pragma unroll
            for (int nt = 0; nt < 4; nt++) {
                vb[nt][0] = __float_as_uint(vs[(nt * 8 + grp) * 260 + n0 + kt * 8 + kc]);
                vb[nt][1] = __float_as_uint(vs[(nt * 8 + grp) * 260 + n0 + kt * 8 + kc + 4]);
            }
            #pragma unroll
            for (int mt = 0; mt < 2; mt++)
                #pragma unroll
                for (int nt = 0; nt < 4; nt++)
                    MMA_TF32(oacc[mt][nt], pa[mt], vb[nt]);
        }
        __syncwarp();
    }

    #pragma unroll
    for (int i = 0; i < 4; i++) {
        denom[i] += __shfl_xor_sync(0xffffffffu, denom[i], 1);
        denom[i] += __shfl_xor_sync(0xffffffffu, denom[i], 2);
        denom[i] = 1.0f / denom[i];
    }
    long ob = ((long)b_ * NTOK + wid * 32) * CC + hh * DH;
    #pragma unroll
    for (int mt = 0; mt < 2; mt++)
        #pragma unroll
        for (int nt = 0; nt < 4; nt++) {
            int r0 = mt * 16 + grp, c0 = nt * 8 + 2 * kc;
            float rd0 = denom[mt * 2 + 0], rd1 = denom[mt * 2 + 1];
            *(float2*)&g_xw[ob + (long)r0 * CC + c0] =
                make_float2(oacc[mt][nt][0] * rd0, oacc[mt][nt][1] * rd0);
            *(float2*)&g_xw[ob + (long)(r0 + 8) * CC + c0] =
                make_float2(oacc[mt][nt][2] * rd1, oacc[mt][nt][3] * rd1);
        }
}

// ---------------- LN(proj) + residual scatter ----------------
__global__ void attn_post_kernel(const float* __restrict__ x,
                                 const float* __restrict__ g, const float* __restrict__ b) {
    int r = blockIdx.x;
    int c = threadIdx.x;
    float v = g_pr[(long)r * CC + c];
    float s1 = v, s2 = v * v;
    #pragma unroll
    for (int o = 16; o; o >>= 1) {
        s1 += __shfl_xor_sync(0xffffffffu, s1, o);
        s2 += __shfl_xor_sync(0xffffffffu, s2, o);
    }
    __shared__ float p1[6], p2[6];
    int w = c >> 5;
    if ((c & 31) == 0) { p1[w] = s1; p2[w] = s2; }
    __syncthreads();
    s1 = p1[0] + p1[1] + p1[2] + p1[3] + p1[4] + p1[5];
    s2 = p2[0] + p2[1] + p2[2] + p2[3] + p2[4] + p2[5];
    float mean = s1 * (1.0f / CC);
    float var = s2 * (1.0f / CC) - mean * mean;
    float ln = (v - mean) * rsqrtf(var + 1e-5f) * g[c] + b[c];
    long dst = src_row(r) * CC + c;
    g_x1[dst] = x[dst] + ln;
}

// ---------------- final LN(fc2) + residual -> output ----------------
__global__ void final_kernel(float* __restrict__ out,
                             const float* __restrict__ g, const float* __restrict__ b) {
    int r = blockIdx.x;
    int c = threadIdx.x;
    float v = g_pr[(long)r * CC + c];
    float s1 = v, s2 = v * v;
    #pragma unroll
    for (int o = 16; o; o >>= 1) {
        s1 += __shfl_xor_sync(0xffffffffu, s1, o);
        s2 += __shfl_xor_sync(0xffffffffu, s2, o);
    }
    __shared__ float p1[6], p2[6];
    int w = c >> 5;
    if ((c & 31) == 0) { p1[w] = s1; p2[w] = s2; }
    __syncthreads();
    s1 = p1[0] + p1[1] + p1[2] + p1[3] + p1[4] + p1[5];
    s2 = p2[0] + p2[1] + p2[2] + p2[3] + p2[4] + p2[5];
    float mean = s1 * (1.0f / CC);
    float var = s2 * (1.0f / CC) - mean * mean;
    float ln = (v - mean) * rsqrtf(var + 1e-5f) * g[c] + b[c];
    out[(long)r * CC + c] = g_x1[(long)r * CC + c] + ln;
}

// ---------------- launch ----------------
extern "C" void kernel_launch(void* const* d_in, const int* in_sizes, int n_in,
                              void* d_out, int out_size) {
    const float* x      = (const float*)d_in[0];
    const float* qkv_w  = (const float*)d_in[1];
    const float* qkv_b  = (const float*)d_in[2];
    const float* proj_w = (const float*)d_in[3];
    const float* proj_b = (const float*)d_in[4];
    const float* cpb_w1 = (const float*)d_in[5];
    const float* cpb_b1 = (const float*)d_in[6];
    const float* cpb_w2 = (const float*)d_in[7];
    const float* ls     = (const float*)d_in[8];
    const float* n1g    = (const float*)d_in[9];
    const float* n1b    = (const float*)d_in[10];
    const float* n2g    = (const float*)d_in[11];
    const float* n2b    = (const float*)d_in[12];
    const float* fc1_w  = (const float*)d_in[13];
    const float* fc1_b  = (const float*)d_in[14];
    const float* fc2_w  = (const float*)d_in[15];
    const float* fc2_b  = (const float*)d_in[16];
    float* out = (float*)d_out;

    cudaFuncSetAttribute(attn_kernel, cudaFuncAttributeMaxDynamicSharedMemorySize, ATTN_SMEM);
    cudaFuncSetAttribute(gemm_qkv_k,  cudaFuncAttributeMaxDynamicSharedMemorySize, GEMM_SMEM);
    cudaFuncSetAttribute(gemm_proj_k, cudaFuncAttributeMaxDynamicSharedMemorySize, GEMM_SMEM);
    cudaFuncSetAttribute(gemm_fc1_k,  cudaFuncAttributeMaxDynamicSharedMemorySize, GEMM_SMEM);
    cudaFuncSetAttribute(gemm_fc2_k,  cudaFuncAttributeMaxDynamicSharedMemorySize, GEMM_SMEM);

    cpb_kernel<<<CPB_M, CPB_H>>>(cpb_w1, cpb_b1, cpb_w2, ls);
    gemm_qkv_k<<<dim3((3 * CC) / 64, MROWS / 256), 256, GEMM_SMEM>>>(x, qkv_w, qkv_b);
    attn_kernel<<<BWIN * HEADS, 256, ATTN_SMEM>>>();
    gemm_proj_k<<<dim3(CC / 64, MROWS / 256), 256, GEMM_SMEM>>>(proj_w, proj_b);
    attn_post_kernel<<<MROWS, 192>>>(x, n1g, n1b);
    gemm_fc1_k<<<dim3(HID / 64, MROWS / 256), 256, GEMM_SMEM>>>(fc1_w, fc1_b);
    gemm_fc2_k<<<dim3(CC / 64, MROWS / 256), 256, GEMM_SMEM>>>(fc2_w, fc2_b);
    final_kernel<<<MROWS, 192>>>(out, n2g, n2b);
}

// round 12
// speedup vs baseline: 1.7066x; 1.1999x over previous
#include <cuda_runtime.h>
#include <cuda_fp16.h>
#include <stdint.h>
#include <math.h>

// ---------------- problem constants ----------------
#define BQ     2
#define TT     8
#define HDIM   64
#define WDIM   64
#define CC     192
#define HEADS  6
#define DH     32
#define NTOK   256
#define NWIN   128
#define BWIN   256
#define MROWS  65536
#define HID    768
#define CPB_M  1575
#define CPB_H  512
#define L2E    1.4426950408889634f

typedef unsigned long long ull;

// ---------------- scratch ----------------
__device__ float g_xw [MROWS * CC];        // attention output (window layout)
__device__ float g_qkv[MROWS * 3 * CC];
__device__ float g_pr [MROWS * CC];
__device__ float g_x1 [MROWS * CC];
__device__ float g_h1 [MROWS * HID];
__device__ float g_tbl[CPB_M * HEADS];
__device__ float g_scale[HEADS];

__device__ __forceinline__ float ex2f(float x) {
    float r;
    asm("ex2.approx.f32 %0, %1;" : "=f"(r) : "f"(x));
    return r;
}

// window row -> source row in (B,T,H,W) layout
__device__ __forceinline__ long src_row(int r) {
    int b_ = r >> 8, n = r & 255;
    int bb = b_ >> 7, w_ = b_ & 127;
    int wt = w_ >> 6, wh = (w_ >> 3) & 7, ww = w_ & 7;
    int it = n >> 6, ih = (n >> 3) & 7, iw = n & 7;
    int t = (wt * 4 + it + 2) & 7;
    int h = (wh * 8 + ih + 4) & 63;
    int w = (ww * 8 + iw + 4) & 63;
    return (long)(((bb * TT + t) * HDIM + h) * WDIM + w);
}

// ---------------- CPB table ----------------
__global__ void cpb_kernel(const float* __restrict__ w1, const float* __restrict__ b1,
                           const float* __restrict__ w2, const float* __restrict__ ls) {
    int m = blockIdx.x;
    int tid = threadIdx.x;
    if (m == 0 && tid < HEADS)
        g_scale[tid] = expf(fminf(ls[tid], logf(100.0f)));

    int i = m / 225, rem = m % 225, j = rem / 15, k = rem % 15;
    float v0 = (float)(i - 3) * (8.0f / 3.0f);
    float v1 = (float)(j - 7) * (8.0f / 7.0f);
    float v2 = (float)(k - 7) * (8.0f / 7.0f);
    const float inv_l8 = 1.0f / log2f(8.0f);
    float c0 = copysignf(log2f(fabsf(v0) + 1.0f) * inv_l8, v0);
    float c1 = copysignf(log2f(fabsf(v1) + 1.0f) * inv_l8, v1);
    float c2 = copysignf(log2f(fabsf(v2) + 1.0f) * inv_l8, v2);

    float h = c0 * w1[tid * 3 + 0] + c1 * w1[tid * 3 + 1] + c2 * w1[tid * 3 + 2] + b1[tid];
    h = fmaxf(h, 0.0f);

    __shared__ float red[CPB_H];
    for (int hh = 0; hh < HEADS; hh++) {
        red[tid] = h * w2[hh * CPB_H + tid];
        __syncthreads();
        for (int s = CPB_H / 2; s > 0; s >>= 1) {
            if (tid < s) red[tid] += red[tid + s];
            __syncthreads();
        }
        if (tid == 0) {
            float t = red[0];
            g_tbl[m * HEADS + hh] = 16.0f / (1.0f + expf(-t));
        }
        __syncthreads();
    }
}

// ---------------- helpers ----------------
__device__ __forceinline__ uint32_t f2tf32(float f) {
    uint32_t u;
    asm("cvt.rna.tf32.f32 %0, %1;" : "=r"(u) : "f"(f));
    return u;
}
__device__ __forceinline__ uint32_t packh2(float x, float y) {
    __half2 h = __floats2half2_rn(x, y);   // lo = x, hi = y
    uint32_t u;
    memcpy(&u, &h, 4);
    return u;
}

#define MMA_F16(acc, af, bf)                                               \
    asm volatile(                                                          \
        "mma.sync.aligned.m16n8k16.row.col.f32.f16.f16.f32 "               \
        "{%0,%1,%2,%3}, {%4,%5,%6,%7}, {%8,%9}, {%0,%1,%2,%3};\n"          \
        : "+f"(acc[0]), "+f"(acc[1]), "+f"(acc[2]), "+f"(acc[3])           \
        : "r"(af[0]), "r"(af[1]), "r"(af[2]), "r"(af[3]),                  \
          "r"(bf[0]), "r"(bf[1]))

#define MMA_TF32(acc, af, bf)                                              \
    asm volatile(                                                          \
        "mma.sync.aligned.m16n8k8.row.col.f32.tf32.tf32.f32 "              \
        "{%0,%1,%2,%3}, {%4,%5,%6,%7}, {%8,%9}, {%0,%1,%2,%3};\n"          \
        : "+f"(acc[0]), "+f"(acc[1]), "+f"(acc[2]), "+f"(acc[3])           \
        : "r"(af[0]), "r"(af[1]), "r"(af[2]), "r"(af[3]),                  \
          "r"(bf[0]), "r"(bf[1]))

// ---------------- fp16 GEMM: 256x64 CTA, 8 warps x (64x32 warp tile), BK=16, 2-stage ----------------
// smem rows hold 8 packed half2 pairs, stride 12 uint32 (conflict-free frag loads).
template <int ACT, bool GATHER>
__device__ __forceinline__ void gemm_tc_body(const float* __restrict__ A, const float* __restrict__ Wt,
                                             const float* __restrict__ bias, float* __restrict__ Cm,
                                             int Nn, int K) {
    __shared__ uint32_t As[2][256][12];
    __shared__ uint32_t Bs[2][64][12];

    int tid = threadIdx.x;        // 0..255
    int lane = tid & 31;
    int warp = tid >> 5;          // 0..7
    int wm = warp >> 1;           // 0..3 -> M offset wm*64
    int wn = warp & 1;            // 0..1 -> N offset wn*32
    int m0 = blockIdx.y * 256;
    int n0 = blockIdx.x * 64;

    int grp = lane >> 2;          // 0..7
    int kc  = lane & 3;           // 0..3

    // global->smem: A 4 float4/thread, B 1 float4/thread (per BK=16 chunk)
    int rA[4], pA[4];
    long abase[4];
    #pragma unroll
    for (int i = 0; i < 4; i++) {
        int e = tid + i * 256;
        rA[i] = e >> 2;                 // row 0..255
        pA[i] = (e & 3) * 2;            // pair col base (0,2,4,6)
        abase[i] = GATHER ? src_row(m0 + rA[i]) * CC : (long)(m0 + rA[i]) * K;
    }
    int rB = tid >> 2, pB = (tid & 3) * 2;
    long bbase = (long)(n0 + rB) * K;

    float acc[4][4][4];
    #pragma unroll
    for (int i = 0; i < 4; i++)
        #pragma unroll
        for (int j = 0; j < 4; j++)
            #pragma unroll
            for (int q = 0; q < 4; q++) acc[i][j][q] = 0.0f;

    int nT = K / 16;
    float4 pa[4], pb;
    #pragma unroll
    for (int i = 0; i < 4; i++) pa[i] = *(const float4*)&A[abase[i] + pA[i] * 2];
    pb = *(const float4*)&Wt[bbase + pB * 2];

    // store stage 0
    #pragma unroll
    for (int i = 0; i < 4; i++) {
        As[0][rA[i]][pA[i] + 0] = packh2(pa[i].x, pa[i].y);
        As[0][rA[i]][pA[i] + 1] = packh2(pa[i].z, pa[i].w);
    }
    Bs[0][rB][pB + 0] = packh2(pb.x, pb.y);
    Bs[0][rB][pB + 1] = packh2(pb.z, pb.w);

    for (int k = 0; k < nT; k++) {
        if (k + 1 < nT) {
            int kn = (k + 1) * 16;
            #pragma unroll
            for (int i = 0; i < 4; i++) pa[i] = *(const float4*)&A[abase[i] + kn + pA[i] * 2];
            pb = *(const float4*)&Wt[bbase + kn + pB * 2];
        }
        __syncthreads();
        uint32_t (*as)[12] = As[k & 1];
        uint32_t (*bs)[12] = Bs[k & 1];

        uint32_t af[4][4];
        #pragma unroll
        for (int mt = 0; mt < 4; mt++) {
            int r = wm * 64 + mt * 16 + grp;
            af[mt][0] = as[r][kc];
            af[mt][1] = as[r + 8][kc];
            af[mt][2] = as[r][kc + 4];
            af[mt][3] = as[r + 8][kc + 4];
        }
        uint32_t bf[4][2];
        #pragma unroll
        for (int nt = 0; nt < 4; nt++) {
            int c = wn * 32 + nt * 8 + grp;
            bf[nt][0] = bs[c][kc];
            bf[nt][1] = bs[c][kc + 4];
        }
        #pragma unroll
        for (int mt = 0; mt < 4; mt++)
            #pragma unroll
            for (int nt = 0; nt < 4; nt++)
                MMA_F16(acc[mt][nt], af[mt], bf[nt]);

        if (k + 1 < nT) {
            uint32_t (*asn)[12] = As[(k + 1) & 1];
            uint32_t (*bsn)[12] = Bs[(k + 1) & 1];
            #pragma unroll
            for (int i = 0; i < 4; i++) {
                asn[rA[i]][pA[i] + 0] = packh2(pa[i].x, pa[i].y);
                asn[rA[i]][pA[i] + 1] = packh2(pa[i].z, pa[i].w);
            }
            bsn[rB][pB + 0] = packh2(pb.x, pb.y);
            bsn[rB][pB + 1] = packh2(pb.z, pb.w);
        }
    }

    #pragma unroll
    for (int mt = 0; mt < 4; mt++) {
        int row = m0 + wm * 64 + mt * 16 + grp;
        #pragma unroll
        for (int nt = 0; nt < 4; nt++) {
            int col = n0 + wn * 32 + nt * 8 + kc * 2;
            float b0 = bias[col], b1 = bias[col + 1];
            float c0 = acc[mt][nt][0] + b0;
            float c1 = acc[mt][nt][1] + b1;
            float c2 = acc[mt][nt][2] + b0;
            float c3 = acc[mt][nt][3] + b1;
            if (ACT == 1) {
                c0 = 0.5f * c0 * (1.0f + erff(c0 * 0.70710678118654752f));
                c1 = 0.5f * c1 * (1.0f + erff(c1 * 0.70710678118654752f));
                c2 = 0.5f * c2 * (1.0f + erff(c2 * 0.70710678118654752f));
                c3 = 0.5f * c3 * (1.0f + erff(c3 * 0.70710678118654752f));
            }
            *(float2*)&Cm[(long)row * Nn + col] = make_float2(c0, c1);
            *(float2*)&Cm[(long)(row + 8) * Nn + col] = make_float2(c2, c3);
        }
    }
}

__global__ void __launch_bounds__(256, 2) gemm_qkv_k (const float* X, const float* Wt, const float* b) { gemm_tc_body<0, true >(X,    Wt, b, g_qkv, 3 * CC, CC); }
__global__ void __launch_bounds__(256, 2) gemm_proj_k(const float* Wt, const float* b)                 { gemm_tc_body<0, false>(g_xw, Wt, b, g_pr,  CC,     CC); }
__global__ void __launch_bounds__(256, 2) gemm_fc1_k (const float* Wt, const float* b)                 { gemm_tc_body<1, false>(g_x1, Wt, b, g_h1,  HID,    CC); }
__global__ void __launch_bounds__(256, 2) gemm_fc2_k (const float* Wt, const float* b)                 { gemm_tc_body<0, false>(g_h1, Wt, b, g_pr,  CC,    HID); }

// ---------------- tensor-core windowed attention (unchanged from R8/R9) ----------------
#define ATTN_SMEM 113312

__global__ void __launch_bounds__(256, 2) attn_kernel() {
    extern __shared__ char smraw[];
    uint32_t* ks  = (uint32_t*)smraw;
    float*    vs  = (float*)(smraw + 36864);
    float*    ps  = (float*)(smraw + 70144);
    float*    tblp = (float*)(smraw + 104960);
    uint32_t* jrs = (uint32_t*)(smraw + 111264);
    uint32_t* cjrs = (uint32_t*)(smraw + 112288);

    int b_ = blockIdx.x / HEADS;
    int hh = blockIdx.x % HEADS;
    int tid = threadIdx.x;
    int lane = tid & 31;
    int wid = tid >> 5;
    int grp = lane >> 2, kc = lane & 3;

    float scale_h = g_scale[hh];
    float Mh = scale_h + 16.0f;

    for (int i = tid; i < CPB_M; i += 256)
        tblp[i] = g_tbl[i * HEADS + hh] * L2E - Mh * L2E;
    if (tid == 0) tblp[CPB_M] = -1000.0f;

    {
        int n = tid;
        int w_ = b_ & 127;
        int wt = w_ >> 6, wh = (w_ >> 3) & 7, ww = w_ & 7;
        int it = n >> 6, ih = (n >> 3) & 7, iw = n & 7;
        int ts = wt * 4 + it, hs = wh * 8 + ih, wv = ww * 8 + iw;
        int dt = (ts < 4) ? 0 : (ts < 6 ? 1 : 2);
        int dh = (hs < 56) ? 0 : (hs < 60 ? 1 : 2);
        int dw = (wv < 56) ? 0 : (wv < 60 ? 1 : 2);
        uint32_t reg = (uint32_t)(dt * 9 + dh * 3 + dw);
        jrs[n]  = (uint32_t)(it * 225 + ih * 15 + iw) | (reg << 20);
        cjrs[n] = (uint32_t)((it + 3) * 225 + (ih + 7) * 15 + (iw + 7)) | (reg << 20);
    }

    {
        int key = tid;
        long base = ((long)b_ * NTOK + key) * (3 * CC) + hh * DH;
        const float4* kp4 = (const float4*)&g_qkv[base + CC];
        const float4* vp4 = (const float4*)&g_qkv[base + 2 * CC];
        float4 kv[8];
        float ss = 0.0f;
        #pragma unroll
        for (int f = 0; f < 8; f++) {
            kv[f] = kp4[f];
            ss += kv[f].x * kv[f].x + kv[f].y * kv[f].y + kv[f].z * kv[f].z + kv[f].w * kv[f].w;
        }
        float rn = 1.0f / fmaxf(sqrtf(ss), 1e-12f);
        #pragma unroll
        for (int f = 0; f < 8; f++) {
            ks[key * 36 + f * 4 + 0] = f2tf32(kv[f].x * rn);
            ks[key * 36 + f * 4 + 1] = f2tf32(kv[f].y * rn);
            ks[key * 36 + f * 4 + 2] = f2tf32(kv[f].z * rn);
            ks[key * 36 + f * 4 + 3] = f2tf32(kv[f].w * rn);
        }
        #pragma unroll
        for (int f = 0; f < 8; f++) {
            float4 v = vp4[f];
            vs[(f * 4 + 0) * 260 + key] = v.x;
            vs[(f * 4 + 1) * 260 + key] = v.y;
            vs[(f * 4 + 2) * 260 + key] = v.z;
            vs[(f * 4 + 3) * 260 + key] = v.w;
        }
    }
    __syncthreads();

    float* myps = ps + wid * (32 * 34);
    {
        long qb = ((long)b_ * NTOK + wid * 32 + lane) * (3 * CC) + hh * DH;
        const float4* qp4 = (const float4*)&g_qkv[qb];
        float4 qv[8];
        float ss = 0.0f;
        #pragma unroll
        for (int f = 0; f < 8; f++) {
            qv[f] = qp4[f];
            ss += qv[f].x * qv[f].x + qv[f].y * qv[f].y + qv[f].z * qv[f].z + qv[f].w * qv[f].w;
        }
        float rn = scale_h / fmaxf(sqrtf(ss), 1e-12f);
        #pragma unroll
        for (int f = 0; f < 8; f++) {
            myps[lane * 34 + f * 4 + 0] = qv[f].x * rn;
            myps[lane * 34 + f * 4 + 1] = qv[f].y * rn;
            myps[lane * 34 + f * 4 + 2] = qv[f].z * rn;
            myps[lane * 34 + f * 4 + 3] = qv[f].w * rn;
        }
    }
    __syncwarp();
    uint32_t qa[2][4][4];
    #pragma unroll
    for (int mt = 0; mt < 2; mt++)
        #pragma unroll
        for (int kt = 0; kt < 4; kt++) {
            int r0 = mt * 16 + grp, c0 = kt * 8 + kc;
            qa[mt][kt][0] = f2tf32(myps[r0 * 34 + c0]);
            qa[mt][kt][1] = f2tf32(myps[(r0 + 8) * 34 + c0]);
            qa[mt][kt][2] = f2tf32(myps[r0 * 34 + c0 + 4]);
            qa[mt][kt][3] = f2tf32(myps[(r0 + 8) * 34 + c0 + 4]);
        }
    __syncwarp();

    uint32_t mycjr[4];
    #pragma unroll
    for (int i = 0; i < 4; i++)
        mycjr[i] = cjrs[wid * 32 + ((i >> 1) * 16 + (i & 1) * 8 + grp)];

    float denom[4] = {0.0f, 0.0f, 0.0f, 0.0f};
    float oacc[2][4][4];
    #pragma unroll
    for (int mt = 0; mt < 2; mt++)
        #pragma unroll
        for (int nt = 0; nt < 4; nt++)
            #pragma unroll
            for (int q = 0; q < 4; q++) oacc[mt][nt][q] = 0.0f;

    for (int ch = 0; ch < 8; ch++) {
        int n0 = ch * 32;
        float s[2][4][4];
        #pragma unroll
        for (int mt = 0; mt < 2; mt++)
            #pragma unroll
            for (int nt = 0; nt < 4; nt++)
                #pragma unroll
                for (int q = 0; q < 4; q++) s[mt][nt][q] = 0.0f;
        #pragma unroll
        for (int kt = 0; kt < 4; kt++) {
            uint32_t kb[4][2];
            #pragma unroll
            for (int nt = 0; nt < 4; nt++) {
                int krow = n0 + nt * 8 + grp;
                kb[nt][0] = ks[krow * 36 + kt * 8 + kc];
                kb[nt][1] = ks[krow * 36 + kt * 8 + kc + 4];
            }
            #pragma unroll
            for (int mt = 0; mt < 2; mt++)
                #pragma unroll
                for (int nt = 0; nt < 4; nt++)
                    MMA_TF32(s[mt][nt], qa[mt][kt], kb[nt]);
        }
        #pragma unroll
        for (int nt = 0; nt < 4; nt++) {
            int k0 = n0 + nt * 8 + 2 * kc;
            uint32_t jr0 = jrs[k0], jr1 = jrs[k0 + 1];
            #pragma unroll
            for (int mt = 0; mt < 2; mt++)
                #pragma unroll
                for (int h = 0; h < 2; h++) {
                    uint32_t mj = mycjr[mt * 2 + h];
                    uint32_t d0 = mj - jr0, x0 = mj ^ jr0;
                    uint32_t d1 = mj - jr1, x1 = mj ^ jr1;
                    int i0 = (x0 < (1u << 20)) ? (int)(d0 & 0xFFFFFu) : CPB_M;
                    int i1 = (x1 < (1u << 20)) ? (int)(d1 & 0xFFFFFu) : CPB_M;
                    float p0 = ex2f(s[mt][nt][h * 2 + 0] * L2E + tblp[i0]);
                    float p1 = ex2f(s[mt][nt][h * 2 + 1] * L2E + tblp[i1]);
                    denom[mt * 2 + h] += p0 + p1;
                    int row = mt * 16 + h * 8 + grp;
                    *(float2*)&myps[row * 34 + nt * 8 + 2 * kc] = make_float2(p0, p1);
                }
        }
        __syncwarp();
        #pragma unroll
        for (int kt = 0; kt < 4; kt++) {
            uint32_t pa[2][4], vb[4][2];
            #pragma unroll
            for (int mt = 0; mt < 2; mt++) {
                int r0 = mt * 16 + grp, c0 = kt * 8 + kc;
                pa[mt][0] = __float_as_uint(myps[r0 * 34 + c0]);
                pa[mt][1] = __float_as_uint(myps[(r0 + 8) * 34 + c0]);
                pa[mt][2] = __float_as_uint(myps[r0 * 34 + c0 + 4]);
                pa[mt][3] = __float_as_uint(myps[(r0 + 8) * 34 + c0 + 4]);
            }
            #pragma unroll
            for (int nt = 0; nt < 4; nt++) {
                vb[nt][0] = __float_as_uint(vs[(nt * 8 + grp) * 260 + n0 + kt * 8 + kc]);
                vb[nt][1] = __float_as_uint(vs[(nt * 8 + grp) * 260 + n0 + kt * 8 + kc + 4]);
            }
            #pragma unroll
            for (int mt = 0; mt < 2; mt++)
                #pragma unroll
                for (int nt = 0; nt < 4; nt++)
                    MMA_TF32(oacc[mt][nt], pa[mt], vb[nt]);
        }
        __syncwarp();
    }

    #pragma unroll
    for (int i = 0; i < 4; i++) {
        denom[i] += __shfl_xor_sync(0xffffffffu, denom[i], 1);
        denom[i] += __shfl_xor_sync(0xffffffffu, denom[i], 2);
        denom[i] = 1.0f / denom[i];
    }
    long ob = ((long)b_ * NTOK + wid * 32) * CC + hh * DH;
    #pragma unroll
    for (int mt = 0; mt < 2; mt++)
        #pragma unroll
        for (int nt = 0; nt < 4; nt++) {
            int r0 = mt * 16 + grp, c0 = nt * 8 + 2 * kc;
            float rd0 = denom[mt * 2 + 0], rd1 = denom[mt * 2 + 1];
            *(float2*)&g_xw[ob + (long)r0 * CC + c0] =
                make_float2(oacc[mt][nt][0] * rd0, oacc[mt][nt][1] * rd0);
            *(float2*)&g_xw[ob + (long)(r0 + 8) * CC + c0] =
                make_float2(oacc[mt][nt][2] * rd1, oacc[mt][nt][3] * rd1);
        }
}

// ---------------- LN(proj) + residual scatter ----------------
__global__ void attn_post_kernel(const float* __restrict__ x,
                                 const float* __restrict__ g, const float* __restrict__ b) {
    int r = blockIdx.x;
    int c = threadIdx.x;
    float v = g_pr[(long)r * CC + c];
    float s1 = v, s2 = v * v;
    #pragma unroll
    for (int o = 16; o; o >>= 1) {
        s1 += __shfl_xor_sync(0xffffffffu, s1, o);
        s2 += __shfl_xor_sync(0xffffffffu, s2, o);
    }
    __shared__ float p1[6], p2[6];
    int w = c >> 5;
    if ((c & 31) == 0) { p1[w] = s1; p2[w] = s2; }
    __syncthreads();
    s1 = p1[0] + p1[1] + p1[2] + p1[3] + p1[4] + p1[5];
    s2 = p2[0] + p2[1] + p2[2] + p2[3] + p2[4] + p2[5];
    float mean = s1 * (1.0f / CC);
    float var = s2 * (1.0f / CC) - mean * mean;
    float ln = (v - mean) * rsqrtf(var + 1e-5f) * g[c] + b[c];
    long dst = src_row(r) * CC + c;
    g_x1[dst] = x[dst] + ln;
}

// ---------------- final LN(fc2) + residual -> output ----------------
__global__ void final_kernel(float* __restrict__ out,
                             const float* __restrict__ g, const float* __restrict__ b) {
    int r = blockIdx.x;
    int c = threadIdx.x;
    float v = g_pr[(long)r * CC + c];
    float s1 = v, s2 = v * v;
    #pragma unroll
    for (int o = 16; o; o >>= 1) {
        s1 += __shfl_xor_sync(0xffffffffu, s1, o);
        s2 += __shfl_xor_sync(0xffffffffu, s2, o);
    }
    __shared__ float p1[6], p2[6];
    int w = c >> 5;
    if ((c & 31) == 0) { p1[w] = s1; p2[w] = s2; }
    __syncthreads();
    s1 = p1[0] + p1[1] + p1[2] + p1[3] + p1[4] + p1[5];
    s2 = p2[0] + p2[1] + p2[2] + p2[3] + p2[4] + p2[5];
    float mean = s1 * (1.0f / CC);
    float var = s2 * (1.0f / CC) - mean * mean;
    float ln = (v - mean) * rsqrtf(var + 1e-5f) * g[c] + b[c];
    out[(long)r * CC + c] = g_x1[(long)r * CC + c] + ln;
}

// ---------------- launch ----------------
extern "C" void kernel_launch(void* const* d_in, const int* in_sizes, int n_in,
                              void* d_out, int out_size) {
    const float* x      = (const float*)d_in[0];
    const float* qkv_w  = (const float*)d_in[1];
    const float* qkv_b  = (const float*)d_in[2];
    const float* proj_w = (const float*)d_in[3];
    const float* proj_b = (const float*)d_in[4];
    const float* cpb_w1 = (const float*)d_in[5];
    const float* cpb_b1 = (const float*)d_in[6];
    const float* cpb_w2 = (const float*)d_in[7];
    const float* ls     = (const float*)d_in[8];
    const float* n1g    = (const float*)d_in[9];
    const float* n1b    = (const float*)d_in[10];
    const float* n2g    = (const float*)d_in[11];
    const float* n2b    = (const float*)d_in[12];
    const float* fc1_w  = (const float*)d_in[13];
    const float* fc1_b  = (const float*)d_in[14];
    const float* fc2_w  = (const float*)d_in[15];
    const float* fc2_b  = (const float*)d_in[16];
    float* out = (float*)d_out;

    cudaFuncSetAttribute(attn_kernel, cudaFuncAttributeMaxDynamicSharedMemorySize, ATTN_SMEM);

    cpb_kernel<<<CPB_M, CPB_H>>>(cpb_w1, cpb_b1, cpb_w2, ls);
    gemm_qkv_k<<<dim3((3 * CC) / 64, MROWS / 256), 256>>>(x, qkv_w, qkv_b);
    attn_kernel<<<BWIN * HEADS, 256, ATTN_SMEM>>>();
    gemm_proj_k<<<dim3(CC / 64, MROWS / 256), 256>>>(proj_w, proj_b);
    attn_post_kernel<<<MROWS, 192>>>(x, n1g, n1b);
    gemm_fc1_k<<<dim3(HID / 64, MROWS / 256), 256>>>(fc1_w, fc1_b);
    gemm_fc2_k<<<dim3(CC / 64, MROWS / 256), 256>>>(fc2_w, fc2_b);
    final_kernel<<<MROWS, 192>>>(out, n2g, n2b);
}

// round 14
// speedup vs baseline: 1.7592x; 1.0308x over previous
#include <cuda_runtime.h>
#include <cuda_fp16.h>
#include <stdint.h>
#include <math.h>

// ---------------- problem constants ----------------
#define BQ     2
#define TT     8
#define HDIM   64
#define WDIM   64
#define CC     192
#define HEADS  6
#define DH     32
#define NTOK   256
#define NWIN   128
#define BWIN   256
#define MROWS  65536
#define HID    768
#define CPB_M  1575
#define CPB_H  512
#define L2E    1.4426950408889634f

typedef unsigned long long ull;

// ---------------- scratch ----------------
__device__ float g_xw [MROWS * CC];        // attention output (window layout)
__device__ float g_qkv[MROWS * 3 * CC];
__device__ float g_pr [MROWS * CC];
__device__ float g_x1 [MROWS * CC];
__device__ float g_h1 [MROWS * HID];
__device__ float g_tbl[CPB_M * HEADS];
__device__ float g_scale[HEADS];

__device__ __forceinline__ float ex2f(float x) {
    float r;
    asm("ex2.approx.f32 %0, %1;" : "=f"(r) : "f"(x));
    return r;
}

// window row -> source row in (B,T,H,W) layout
__device__ __forceinline__ long src_row(int r) {
    int b_ = r >> 8, n = r & 255;
    int bb = b_ >> 7, w_ = b_ & 127;
    int wt = w_ >> 6, wh = (w_ >> 3) & 7, ww = w_ & 7;
    int it = n >> 6, ih = (n >> 3) & 7, iw = n & 7;
    int t = (wt * 4 + it + 2) & 7;
    int h = (wh * 8 + ih + 4) & 63;
    int w = (ww * 8 + iw + 4) & 63;
    return (long)(((bb * TT + t) * HDIM + h) * WDIM + w);
}

// ---------------- CPB table ----------------
__global__ void cpb_kernel(const float* __restrict__ w1, const float* __restrict__ b1,
                           const float* __restrict__ w2, const float* __restrict__ ls) {
    int m = blockIdx.x;
    int tid = threadIdx.x;
    if (m == 0 && tid < HEADS)
        g_scale[tid] = expf(fminf(ls[tid], logf(100.0f)));

    int i = m / 225, rem = m % 225, j = rem / 15, k = rem % 15;
    float v0 = (float)(i - 3) * (8.0f / 3.0f);
    float v1 = (float)(j - 7) * (8.0f / 7.0f);
    float v2 = (float)(k - 7) * (8.0f / 7.0f);
    const float inv_l8 = 1.0f / log2f(8.0f);
    float c0 = copysignf(log2f(fabsf(v0) + 1.0f) * inv_l8, v0);
    float c1 = copysignf(log2f(fabsf(v1) + 1.0f) * inv_l8, v1);
    float c2 = copysignf(log2f(fabsf(v2) + 1.0f) * inv_l8, v2);

    float h = c0 * w1[tid * 3 + 0] + c1 * w1[tid * 3 + 1] + c2 * w1[tid * 3 + 2] + b1[tid];
    h = fmaxf(h, 0.0f);

    __shared__ float red[CPB_H];
    for (int hh = 0; hh < HEADS; hh++) {
        red[tid] = h * w2[hh * CPB_H + tid];
        __syncthreads();
        for (int s = CPB_H / 2; s > 0; s >>= 1) {
            if (tid < s) red[tid] += red[tid + s];
            __syncthreads();
        }
        if (tid == 0) {
            float t = red[0];
            g_tbl[m * HEADS + hh] = 16.0f / (1.0f + expf(-t));
        }
        __syncthreads();
    }
}

// ---------------- helpers ----------------
__device__ __forceinline__ uint32_t f2tf32(float f) {
    uint32_t u;
    asm("cvt.rna.tf32.f32 %0, %1;" : "=r"(u) : "f"(f));
    return u;
}
__device__ __forceinline__ uint32_t packh2(float x, float y) {
    __half2 h = __floats2half2_rn(x, y);   // lo = x, hi = y
    uint32_t u;
    memcpy(&u, &h, 4);
    return u;
}
__device__ __forceinline__ uint32_t s2u(const void* p) {
    uint32_t a;
    asm("{ .reg .u64 t; cvta.to.shared.u64 t, %1; cvt.u32.u64 %0, t; }" : "=r"(a) : "l"(p));
    return a;
}

#define MMA_F16(acc, af, bf)                                               \
    asm volatile(                                                          \
        "mma.sync.aligned.m16n8k16.row.col.f32.f16.f16.f32 "               \
        "{%0,%1,%2,%3}, {%4,%5,%6,%7}, {%8,%9}, {%0,%1,%2,%3};\n"          \
        : "+f"(acc[0]), "+f"(acc[1]), "+f"(acc[2]), "+f"(acc[3])           \
        : "r"(af[0]), "r"(af[1]), "r"(af[2]), "r"(af[3]),                  \
          "r"(bf[0]), "r"(bf[1]))

#define MMA_TF32(acc, af, bf)                                              \
    asm volatile(                                                          \
        "mma.sync.aligned.m16n8k8.row.col.f32.tf32.tf32.f32 "              \
        "{%0,%1,%2,%3}, {%4,%5,%6,%7}, {%8,%9}, {%0,%1,%2,%3};\n"          \
        : "+f"(acc[0]), "+f"(acc[1]), "+f"(acc[2]), "+f"(acc[3])           \
        : "r"(af[0]), "r"(af[1]), "r"(af[2]), "r"(af[3]),                  \
          "r"(bf[0]), "r"(bf[1]))

#define LDSM_X4(r0, r1, r2, r3, addr)                                      \
    asm volatile("ldmatrix.sync.aligned.m8n8.x4.shared.b16 "               \
                 "{%0,%1,%2,%3}, [%4];"                                    \
                 : "=r"(r0), "=r"(r1), "=r"(r2), "=r"(r3) : "r"(addr))

// ---------------- fp16 GEMM: 256x64 CTA, 8 warps x (64x32 warp tile), BK=16, 2-stage, LDSM ----------------
template <int ACT, bool GATHER>
__device__ __forceinline__ void gemm_tc_body(const float* __restrict__ A, const float* __restrict__ Wt,
                                             const float* __restrict__ bias, float* __restrict__ Cm,
                                             int Nn, int K) {
    __shared__ uint32_t As[2][256][12];
    __shared__ uint32_t Bs[2][64][12];

    int tid = threadIdx.x;        // 0..255
    int lane = tid & 31;
    int warp = tid >> 5;          // 0..7
    int wm = warp >> 1;           // 0..3 -> M offset wm*64
    int wn = warp & 1;            // 0..1 -> N offset wn*32
    int m0 = blockIdx.y * 256;
    int n0 = blockIdx.x * 64;

    int grp = lane >> 2;          // 0..7
    int kc  = lane & 3;           // 0..3

    // global->smem: A 4 float4/thread, B 1 float4/thread (per BK=16 chunk)
    int rA[4], pA[4];
    long abase[4];
    #pragma unroll
    for (int i = 0; i < 4; i++) {
        int e = tid + i * 256;
        rA[i] = e >> 2;                 // row 0..255
        pA[i] = (e & 3) * 2;            // pair col base (0,2,4,6)
        abase[i] = GATHER ? src_row(m0 + rA[i]) * CC : (long)(m0 + rA[i]) * K;
    }
    int rB = tid >> 2, pB = (tid & 3) * 2;
    long bbase = (long)(n0 + rB) * K;

    // LDSM lane addresses (per stage)
    //   A tiles: row = wm*64 + mt*16 + (lane&15), k-half = lane>>4  (uint col off = (lane>>4)*4)
    //   B tiles: n = wn*32 + bt*16 + ((lane>>4)<<3) + (lane&7), k-half = (lane>>3)&1
    uint32_t aaddr[2][4], baddr[2][2];
    #pragma unroll
    for (int st = 0; st < 2; st++) {
        #pragma unroll
        for (int mt = 0; mt < 4; mt++) {
            int r = wm * 64 + mt * 16 + (lane & 15);
            aaddr[st][mt] = s2u(&As[st][r][(lane >> 4) * 4]);
        }
        #pragma unroll
        for (int bt = 0; bt < 2; bt++) {
            int c = wn * 32 + bt * 16 + ((lane >> 4) << 3) + (lane & 7);
            baddr[st][bt] = s2u(&Bs[st][c][((lane >> 3) & 1) * 4]);
        }
    }

    float acc[4][4][4];
    #pragma unroll
    for (int i = 0; i < 4; i++)
        #pragma unroll
        for (int j = 0; j < 4; j++)
            #pragma unroll
            for (int q = 0; q < 4; q++) acc[i][j][q] = 0.0f;

    int nT = K / 16;
    float4 pa[4], pb;
    #pragma unroll
    for (int i = 0; i < 4; i++) pa[i] = *(const float4*)&A[abase[i] + pA[i] * 2];
    pb = *(const float4*)&Wt[bbase + pB * 2];

    // store stage 0
    #pragma unroll
    for (int i = 0; i < 4; i++) {
        As[0][rA[i]][pA[i] + 0] = packh2(pa[i].x, pa[i].y);
        As[0][rA[i]][pA[i] + 1] = packh2(pa[i].z, pa[i].w);
    }
    Bs[0][rB][pB + 0] = packh2(pb.x, pb.y);
    Bs[0][rB][pB + 1] = packh2(pb.z, pb.w);

    for (int k = 0; k < nT; k++) {
        if (k + 1 < nT) {
            int kn = (k + 1) * 16;
            #pragma unroll
            for (int i = 0; i < 4; i++) pa[i] = *(const float4*)&A[abase[i] + kn + pA[i] * 2];
            pb = *(const float4*)&Wt[bbase + kn + pB * 2];
        }
        __syncthreads();
        int st = k & 1;

        uint32_t af[4][4];
        #pragma unroll
        for (int mt = 0; mt < 4; mt++)
            LDSM_X4(af[mt][0], af[mt][1], af[mt][2], af[mt][3], aaddr[st][mt]);
        uint32_t bf[4][2];
        #pragma unroll
        for (int bt = 0; bt < 2; bt++) {
            uint32_t r0, r1, r2, r3;
            LDSM_X4(r0, r1, r2, r3, baddr[st][bt]);
            bf[bt * 2 + 0][0] = r0; bf[bt * 2 + 0][1] = r1;
            bf[bt * 2 + 1][0] = r2; bf[bt * 2 + 1][1] = r3;
        }
        #pragma unroll
        for (int mt = 0; mt < 4; mt++)
            #pragma unroll
            for (int nt = 0; nt < 4; nt++)
                MMA_F16(acc[mt][nt], af[mt], bf[nt]);

        if (k + 1 < nT) {
            uint32_t (*asn)[12] = As[(k + 1) & 1];
            uint32_t (*bsn)[12] = Bs[(k + 1) & 1];
            #pragma unroll
            for (int i = 0; i < 4; i++) {
                asn[rA[i]][pA[i] + 0] = packh2(pa[i].x, pa[i].y);
                asn[rA[i]][pA[i] + 1] = packh2(pa[i].z, pa[i].w);
            }
            bsn[rB][pB + 0] = packh2(pb.x, pb.y);
            bsn[rB][pB + 1] = packh2(pb.z, pb.w);
        }
    }

    #pragma unroll
    for (int mt = 0; mt < 4; mt++) {
        int row = m0 + wm * 64 + mt * 16 + grp;
        #pragma unroll
        for (int nt = 0; nt < 4; nt++) {
            int col = n0 + wn * 32 + nt * 8 + kc * 2;
            float b0 = bias[col], b1 = bias[col + 1];
            float c0 = acc[mt][nt][0] + b0;
            float c1 = acc[mt][nt][1] + b1;
            float c2 = acc[mt][nt][2] + b0;
            float c3 = acc[mt][nt][3] + b1;
            if (ACT == 1) {
                c0 = 0.5f * c0 * (1.0f + erff(c0 * 0.70710678118654752f));
                c1 = 0.5f * c1 * (1.0f + erff(c1 * 0.70710678118654752f));
                c2 = 0.5f * c2 * (1.0f + erff(c2 * 0.70710678118654752f));
                c3 = 0.5f * c3 * (1.0f + erff(c3 * 0.70710678118654752f));
            }
            *(float2*)&Cm[(long)row * Nn + col] = make_float2(c0, c1);
            *(float2*)&Cm[(long)(row + 8) * Nn + col] = make_float2(c2, c3);
        }
    }
}

__global__ void __launch_bounds__(256, 2) gemm_qkv_k (const float* X, const float* Wt, const float* b) { gemm_tc_body<0, true >(X,    Wt, b, g_qkv, 3 * CC, CC); }
__global__ void __launch_bounds__(256, 2) gemm_proj_k(const float* Wt, const float* b)                 { gemm_tc_body<0, false>(g_xw, Wt, b, g_pr,  CC,     CC); }
__global__ void __launch_bounds__(256, 2) gemm_fc1_k (const float* Wt, const float* b)                 { gemm_tc_body<1, false>(g_x1, Wt, b, g_h1,  HID,    CC); }
__global__ void __launch_bounds__(256, 2) gemm_fc2_k (const float* Wt, const float* b)                 { gemm_tc_body<0, false>(g_h1, Wt, b, g_pr,  CC,    HID); }

// ---------------- tensor-core windowed attention (unchanged) ----------------
#define ATTN_SMEM 113312

__global__ void __launch_bounds__(256, 2) attn_kernel() {
    extern __shared__ char smraw[];
    uint32_t* ks  = (uint32_t*)smraw;
    float*    vs  = (float*)(smraw + 36864);
    float*    ps  = (float*)(smraw + 70144);
    float*    tblp = (float*)(smraw + 104960);
    uint32_t* jrs = (uint32_t*)(smraw + 111264);
    uint32_t* cjrs = (uint32_t*)(smraw + 112288);

    int b_ = blockIdx.x / HEADS;
    int hh = blockIdx.x % HEADS;
    int tid = threadIdx.x;
    int lane = tid & 31;
    int wid = tid >> 5;
    int grp = lane >> 2, kc = lane & 3;

    float scale_h = g_scale[hh];
    float Mh = scale_h + 16.0f;

    for (int i = tid; i < CPB_M; i += 256)
        tblp[i] = g_tbl[i * HEADS + hh] * L2E - Mh * L2E;
    if (tid == 0) tblp[CPB_M] = -1000.0f;

    {
        int n = tid;
        int w_ = b_ & 127;
        int wt = w_ >> 6, wh = (w_ >> 3) & 7, ww = w_ & 7;
        int it = n >> 6, ih = (n >> 3) & 7, iw = n & 7;
        int ts = wt * 4 + it, hs = wh * 8 + ih, wv = ww * 8 + iw;
        int dt = (ts < 4) ? 0 : (ts < 6 ? 1 : 2);
        int dh = (hs < 56) ? 0 : (hs < 60 ? 1 : 2);
        int dw = (wv < 56) ? 0 : (wv < 60 ? 1 : 2);
        uint32_t reg = (uint32_t)(dt * 9 + dh * 3 + dw);
        jrs[n]  = (uint32_t)(it * 225 + ih * 15 + iw) | (reg << 20);
        cjrs[n] = (uint32_t)((it + 3) * 225 + (ih + 7) * 15 + (iw + 7)) | (reg << 20);
    }

    {
        int key = tid;
        long base = ((long)b_ * NTOK + key) * (3 * CC) + hh * DH;
        const float4* kp4 = (const float4*)&g_qkv[base + CC];
        const float4* vp4 = (const float4*)&g_qkv[base + 2 * CC];
        float4 kv[8];
        float ss = 0.0f;
        #pragma unroll
        for (int f = 0; f < 8; f++) {
            kv[f] = kp4[f];
            ss += kv[f].x * kv[f].x + kv[f].y * kv[f].y + kv[f].z * kv[f].z + kv[f].w * kv[f].w;
        }
        float rn = 1.0f / fmaxf(sqrtf(ss), 1e-12f);
        #pragma unroll
        for (int f = 0; f < 8; f++) {
            ks[key * 36 + f * 4 + 0] = f2tf32(kv[f].x * rn);
            ks[key * 36 + f * 4 + 1] = f2tf32(kv[f].y * rn);
            ks[key * 36 + f * 4 + 2] = f2tf32(kv[f].z * rn);
            ks[key * 36 + f * 4 + 3] = f2tf32(kv[f].w * rn);
        }
        #pragma unroll
        for (int f = 0; f < 8; f++) {
            float4 v = vp4[f];
            vs[(f * 4 + 0) * 260 + key] = v.x;
            vs[(f * 4 + 1) * 260 + key] = v.y;
            vs[(f * 4 + 2) * 260 + key] = v.z;
            vs[(f * 4 + 3) * 260 + key] = v.w;
        }
    }
    __syncthreads();

    float* myps = ps + wid * (32 * 34);
    {
        long qb = ((long)b_ * NTOK + wid * 32 + lane) * (3 * CC) + hh * DH;
        const float4* qp4 = (const float4*)&g_qkv[qb];
        float4 qv[8];
        float ss = 0.0f;
        #pragma unroll
        for (int f = 0; f < 8; f++) {
            qv[f] = qp4[f];
            ss += qv[f].x * qv[f].x + qv[f].y * qv[f].y + qv[f].z * qv[f].z + qv[f].w * qv[f].w;
        }
        float rn = scale_h / fmaxf(sqrtf(ss), 1e-12f);
        #pragma unroll
        for (int f = 0; f < 8; f++) {
            myps[lane * 34 + f * 4 + 0] = qv[f].x * rn;
            myps[lane * 34 + f * 4 + 1] = qv[f].y * rn;
            myps[lane * 34 + f * 4 + 2] = qv[f].z * rn;
            myps[lane * 34 + f * 4 + 3] = qv[f].w * rn;
        }
    }
    __syncwarp();
    uint32_t qa[2][4][4];
    #pragma unroll
    for (int mt = 0; mt < 2; mt++)
        #pragma unroll
        for (int kt = 0; kt < 4; kt++) {
            int r0 = mt * 16 + grp, c0 = kt * 8 + kc;
            qa[mt][kt][0] = f2tf32(myps[r0 * 34 + c0]);
            qa[mt][kt][1] = f2tf32(myps[(r0 + 8) * 34 + c0]);
            qa[mt][kt][2] = f2tf32(myps[r0 * 34 + c0 + 4]);
            qa[mt][kt][3] = f2tf32(myps[(r0 + 8) * 34 + c0 + 4]);
        }
    __syncwarp();

    uint32_t mycjr[4];
    #pragma unroll
    for (int i = 0; i < 4; i++)
        mycjr[i] = cjrs[wid * 32 + ((i >> 1) * 16 + (i & 1) * 8 + grp)];

    float denom[4] = {0.0f, 0.0f, 0.0f, 0.0f};
    float oacc[2][4][4];
    #pragma unroll
    for (int mt = 0; mt < 2; mt++)
        #pragma unroll
        for (int nt = 0; nt < 4; nt++)
            #pragma unroll
            for (int q = 0; q < 4; q++) oacc[mt][nt][q] = 0.0f;

    for (int ch = 0; ch < 8; ch++) {
        int n0 = ch * 32;
        float s[2][4][4];
        #pragma unroll
        for (int mt = 0; mt < 2; mt++)
            #pragma unroll
            for (int nt = 0; nt < 4; nt++)
                #pragma unroll
                for (int q = 0; q < 4; q++) s[mt][nt][q] = 0.0f;
        #pragma unroll
        for (int kt = 0; kt < 4; kt++) {
            uint32_t kb[4][2];
            #pragma unroll
            for (int nt = 0; nt < 4; nt++) {
                int krow = n0 + nt * 8 + grp;
                kb[nt][0] = ks[krow * 36 + kt * 8 + kc];
                kb[nt][1] = ks[krow * 36 + kt * 8 + kc + 4];
            }
            #pragma unroll
            for (int mt = 0; mt < 2; mt++)
                #pragma unroll
                for (int nt = 0; nt < 4; nt++)
                    MMA_TF32(s[mt][nt], qa[mt][kt], kb[nt]);
        }
        #pragma unroll
        for (int nt = 0; nt < 4; nt++) {
            int k0 = n0 + nt * 8 + 2 * kc;
            uint32_t jr0 = jrs[k0], jr1 = jrs[k0 + 1];
            #pragma unroll
            for (int mt = 0; mt < 2; mt++)
                #pragma unroll
                for (int h = 0; h < 2; h++) {
                    uint32_t mj = mycjr[mt * 2 + h];
                    uint32_t d0 = mj - jr0, x0 = mj ^ jr0;
                    uint32_t d1 = mj - jr1, x1 = mj ^ jr1;
                    int i0 = (x0 < (1u << 20)) ? (int)(d0 & 0xFFFFFu) : CPB_M;
                    int i1 = (x1 < (1u << 20)) ? (int)(d1 & 0xFFFFFu) : CPB_M;
                    float p0 = ex2f(s[mt][nt][h * 2 + 0] * L2E + tblp[i0]);
                    float p1 = ex2f(s[mt][nt][h * 2 + 1] * L2E + tblp[i1]);
                    denom[mt * 2 + h] += p0 + p1;
                    int row = mt * 16 + h * 8 + grp;
                    *(float2*)&myps[row * 34 + nt * 8 + 2 * kc] = make_float2(p0, p1);
                }
        }
        __syncwarp();
        #pragma unroll
        for (int kt = 0; kt < 4; kt++) {
            uint32_t pa[2][4], vb[4][2];
            #pragma unroll
            for (int mt = 0; mt < 2; mt++) {
                int r0 = mt * 16 + grp, c0 = kt * 8 + kc;
                pa[mt][0] = __float_as_uint(myps[r0 * 34 + c0]);
                pa[mt][1] = __float_as_uint(myps[(r0 + 8) * 34 + c0]);
                pa[mt][2] = __float_as_uint(myps[r0 * 34 + c0 + 4]);
                pa[mt][3] = __float_as_uint(myps[(r0 + 8) * 34 + c0 + 4]);
            }
            #pragma unroll
            for (int nt = 0; nt < 4; nt++) {
                vb[nt][0] = __float_as_uint(vs[(nt * 8 + grp) * 260 + n0 + kt * 8 + kc]);
                vb[nt][1] = __float_as_uint(vs[(nt * 8 + grp) * 260 + n0 + kt * 8 + kc + 4]);
            }
            #pragma unroll
            for (int mt = 0; mt < 2; mt++)
                #pragma unroll
                for (int nt = 0; nt < 4; nt++)
                    MMA_TF32(oacc[mt][nt], pa[mt], vb[nt]);
        }
        __syncwarp();
    }

    #pragma unroll
    for (int i = 0; i < 4; i++) {
        denom[i] += __shfl_xor_sync(0xffffffffu, denom[i], 1);
        denom[i] += __shfl_xor_sync(0xffffffffu, denom[i], 2);
        denom[i] = 1.0f / denom[i];
    }
    long ob = ((long)b_ * NTOK + wid * 32) * CC + hh * DH;
    #pragma unroll
    for (int mt = 0; mt < 2; mt++)
        #pragma unroll
        for (int nt = 0; nt < 4; nt++) {
            int r0 = mt * 16 + grp, c0 = nt * 8 + 2 * kc;
            float rd0 = denom[mt * 2 + 0], rd1 = denom[mt * 2 + 1];
            *(float2*)&g_xw[ob + (long)r0 * CC + c0] =
                make_float2(oacc[mt][nt][0] * rd0, oacc[mt][nt][1] * rd0);
            *(float2*)&g_xw[ob + (long)(r0 + 8) * CC + c0] =
                make_float2(oacc[mt][nt][2] * rd1, oacc[mt][nt][3] * rd1);
        }
}

// ---------------- LN(proj) + residual scatter ----------------
__global__ void attn_post_kernel(const float* __restrict__ x,
                                 const float* __restrict__ g, const float* __restrict__ b) {
    int r = blockIdx.x;
    int c = threadIdx.x;
    float v = g_pr[(long)r * CC + c];
    float s1 = v, s2 = v * v;
    #pragma unroll
    for (int o = 16; o; o >>= 1) {
        s1 += __shfl_xor_sync(0xffffffffu, s1, o);
        s2 += __shfl_xor_sync(0xffffffffu, s2, o);
    }
    __shared__ float p1[6], p2[6];
    int w = c >> 5;
    if ((c & 31) == 0) { p1[w] = s1; p2[w] = s2; }
    __syncthreads();
    s1 = p1[0] + p1[1] + p1[2] + p1[3] + p1[4] + p1[5];
    s2 = p2[0] + p2[1] + p2[2] + p2[3] + p2[4] + p2[5];
    float mean = s1 * (1.0f / CC);
    float var = s2 * (1.0f / CC) - mean * mean;
    float ln = (v - mean) * rsqrtf(var + 1e-5f) * g[c] + b[c];
    long dst = src_row(r) * CC + c;
    g_x1[dst] = x[dst] + ln;
}

// ---------------- final LN(fc2) + residual -> output ----------------
__global__ void final_kernel(float* __restrict__ out,
                             const float* __restrict__ g, const float* __restrict__ b) {
    int r = blockIdx.x;
    int c = threadIdx.x;
    float v = g_pr[(long)r * CC + c];
    float s1 = v, s2 = v * v;
    #pragma unroll
    for (int o = 16; o; o >>= 1) {
        s1 += __shfl_xor_sync(0xffffffffu, s1, o);
        s2 += __shfl_xor_sync(0xffffffffu, s2, o);
    }
    __shared__ float p1[6], p2[6];
    int w = c >> 5;
    if ((c & 31) == 0) { p1[w] = s1; p2[w] = s2; }
    __syncthreads();
    s1 = p1[0] + p1[1] + p1[2] + p1[3] + p1[4] + p1[5];
    s2 = p2[0] + p2[1] + p2[2] + p2[3] + p2[4] + p2[5];
    float mean = s1 * (1.0f / CC);
    float var = s2 * (1.0f / CC) - mean * mean;
    float ln = (v - mean) * rsqrtf(var + 1e-5f) * g[c] + b[c];
    out[(long)r * CC + c] = g_x1[(long)r * CC + c] + ln;
}

// ---------------- launch ----------------
extern "C" void kernel_launch(void* const* d_in, const int* in_sizes, int n_in,
                              void* d_out, int out_size) {
    const float* x      = (const float*)d_in[0];
    const float* qkv_w  = (const float*)d_in[1];
    const float* qkv_b  = (const float*)d_in[2];
    const float* proj_w = (const float*)d_in[3];
    const float* proj_b = (const float*)d_in[4];
    const float* cpb_w1 = (const float*)d_in[5];
    const float* cpb_b1 = (const float*)d_in[6];
    const float* cpb_w2 = (const float*)d_in[7];
    const float* ls     = (const float*)d_in[8];
    const float* n1g    = (const float*)d_in[9];
    const float* n1b    = (const float*)d_in[10];
    const float* n2g    = (const float*)d_in[11];
    const float* n2b    = (const float*)d_in[12];
    const float* fc1_w  = (const float*)d_in[13];
    const float* fc1_b  = (const float*)d_in[14];
    const float* fc2_w  = (const float*)d_in[15];
    const float* fc2_b  = (const float*)d_in[16];
    float* out = (float*)d_out;

    cudaFuncSetAttribute(attn_kernel, cudaFuncAttributeMaxDynamicSharedMemorySize, ATTN_SMEM);

    cpb_kernel<<<CPB_M, CPB_H>>>(cpb_w1, cpb_b1, cpb_w2, ls);
    gemm_qkv_k<<<dim3((3 * CC) / 64, MROWS / 256), 256>>>(x, qkv_w, qkv_b);
    attn_kernel<<<BWIN * HEADS, 256, ATTN_SMEM>>>();
    gemm_proj_k<<<dim3(CC / 64, MROWS / 256), 256>>>(proj_w, proj_b);
    attn_post_kernel<<<MROWS, 192>>>(x, n1g, n1b);
    gemm_fc1_k<<<dim3(HID / 64, MROWS / 256), 256>>>(fc1_w, fc1_b);
    gemm_fc2_k<<<dim3(CC / 64, MROWS / 256), 256>>>(fc2_w, fc2_b);
    final_kernel<<<MROWS, 192>>>(out, n2g, n2b);
}